// round 5
// baseline (speedup 1.0000x reference)
#include <cuda_runtime.h>
#include <cstdint>
#include <cstdio>

// Problem constants
#define Bq   64
#define Sq   2048
#define INq  208
#define Hq   100
#define Gq   300      // 3*H gate rows
#define OUTq 98
#define Mq   (Bq * Sq)   // 131072 rows

// ---------------------------------------------------------------------------
// Scratch (static __device__ arrays — allocation is forbidden)
// ---------------------------------------------------------------------------
__device__ float g_xg[(size_t)Mq * Gq];  // 157 MB: xg0, then reused for xg1
__device__ float g_y [(size_t)Mq * Hq];  //  52 MB: y0, then reused for y1

#define FMA2(c, a, b) \
    asm("fma.rn.f32x2 %0, %1, %2, %0;" : "+l"(c) : "l"(a), "l"(b))

// ---------------------------------------------------------------------------
// GEMM with bias: C[m][n] = bias[n] + sum_k A[m][k] * W[n][k]
// A: M x K row-major, W: N x K row-major (A @ W^T), C: M x N.
// BM=BN=128, BK=8, 256 threads, 8x8 microtile computed as 8 x (4 f32x2 pairs).
// A is stored PAIR-REPLICATED in SMEM so the (a,a) packed operand is a plain
// LDS (no register repacking). Double-buffered, 1 barrier per K-tile.
// Requires: M % 128 == 0, K % 4 == 0.  (unchanged from round 4)
// ---------------------------------------------------------------------------
#define BM 128
#define BN 128
#define BK 8

__global__ __launch_bounds__(256, 2) void gemm_bias(
    const float* __restrict__ A, const float* __restrict__ W,
    const float* __restrict__ bias, float* __restrict__ C,
    int N, int K)
{
    __shared__ __align__(16) float As[2][BK][2 * BM + 8];  // replicated pairs
    __shared__ __align__(16) float Ws[2][BK][BN + 8];

    const int n0  = blockIdx.x * BN;
    const int m0  = blockIdx.y * BM;
    const int tid = threadIdx.x;
    const int tx  = tid & 15;        // n microtile
    const int ty  = tid >> 4;        // m microtile

    // Loader: each thread owns one row-half: row lr, k-offset lk (float4)
    const int  lr = tid >> 1;
    const int  lk = (tid & 1) * 4;
    const float* Ap = A + (size_t)(m0 + lr) * K + lk;
    const float* Wp = W + (size_t)(n0 + lr) * K + lk;
    const bool wrow = (n0 + lr) < N;

    unsigned long long c[8][4];
#pragma unroll
    for (int i = 0; i < 8; i++)
#pragma unroll
        for (int j = 0; j < 4; j++) c[i][j] = 0ull;

    const int ntiles = (K + BK - 1) / BK;

    // tile 0 load + store (tile 0 is always fully in-bounds on k: K >= 8)
    float4 av = *(const float4*)Ap;
    float4 wv = wrow ? *(const float4*)Wp : make_float4(0.f, 0.f, 0.f, 0.f);
    {
        As[0][lk + 0][2 * lr] = av.x; As[0][lk + 0][2 * lr + 1] = av.x;
        As[0][lk + 1][2 * lr] = av.y; As[0][lk + 1][2 * lr + 1] = av.y;
        As[0][lk + 2][2 * lr] = av.z; As[0][lk + 2][2 * lr + 1] = av.z;
        As[0][lk + 3][2 * lr] = av.w; As[0][lk + 3][2 * lr + 1] = av.w;
        Ws[0][lk + 0][lr] = wv.x; Ws[0][lk + 1][lr] = wv.y;
        Ws[0][lk + 2][lr] = wv.z; Ws[0][lk + 3][lr] = wv.w;
    }
    __syncthreads();

    for (int tile = 0; tile < ntiles; tile++) {
        const int buf = tile & 1;
        // prefetch next tile into regs (guard tail: K%8 may be 4)
        const bool more = (tile + 1) < ntiles;
        if (more) {
            const int k = (tile + 1) * BK + lk;
            const bool kv = k < K;   // K%4==0 so k<K implies k+3<K
            av = kv ? *(const float4*)(Ap + (tile + 1) * BK)
                    : make_float4(0.f, 0.f, 0.f, 0.f);
            wv = (kv && wrow) ? *(const float4*)(Wp + (tile + 1) * BK)
                              : make_float4(0.f, 0.f, 0.f, 0.f);
        }

#pragma unroll
        for (int kk = 0; kk < BK; kk++) {
            const ulonglong2* wsp = (const ulonglong2*)&Ws[buf][kk][tx * 8];
            const ulonglong2 b01 = wsp[0];
            const ulonglong2 b23 = wsp[1];
            const ulonglong2* asp = (const ulonglong2*)&As[buf][kk][ty * 16];
            const ulonglong2 a01 = asp[0];
            const ulonglong2 a23 = asp[1];
            const ulonglong2 a45 = asp[2];
            const ulonglong2 a67 = asp[3];
            unsigned long long a[8] = { a01.x, a01.y, a23.x, a23.y,
                                        a45.x, a45.y, a67.x, a67.y };
            unsigned long long bb[4] = { b01.x, b01.y, b23.x, b23.y };
#pragma unroll
            for (int i = 0; i < 8; i++)
#pragma unroll
                for (int jp = 0; jp < 4; jp++)
                    FMA2(c[i][jp], a[i], bb[jp]);
        }

        if (more) {
            const int nb = buf ^ 1;
            As[nb][lk + 0][2 * lr] = av.x; As[nb][lk + 0][2 * lr + 1] = av.x;
            As[nb][lk + 1][2 * lr] = av.y; As[nb][lk + 1][2 * lr + 1] = av.y;
            As[nb][lk + 2][2 * lr] = av.z; As[nb][lk + 2][2 * lr + 1] = av.z;
            As[nb][lk + 3][2 * lr] = av.w; As[nb][lk + 3][2 * lr + 1] = av.w;
            Ws[nb][lk + 0][lr] = wv.x; Ws[nb][lk + 1][lr] = wv.y;
            Ws[nb][lk + 2][lr] = wv.z; Ws[nb][lk + 3][lr] = wv.w;
            __syncthreads();
        }
    }

#pragma unroll
    for (int i = 0; i < 8; i++) {
        const size_t m = (size_t)m0 + ty * 8 + i;
#pragma unroll
        for (int jp = 0; jp < 4; jp++) {
            const int n = n0 + tx * 8 + 2 * jp;
            float lo, hi;
            asm("mov.b64 {%0, %1}, %2;" : "=f"(lo), "=f"(hi) : "l"(c[i][jp]));
            if (n < N)     C[m * N + n]     = lo + bias[n];
            if (n + 1 < N) C[m * N + n + 1] = hi + bias[n + 1];
        }
    }
}

// ---------------------------------------------------------------------------
// GRU recurrence, FULL-ROW version — no cross-lane reduction at all.
// One CTA per batch element (64 CTAs), 384 threads (12 warps).
//   threads 0..299 : each owns one full gate row g; computes the complete
//                    100-wide dot hg[g] = w_hh[g,:] . h as 50 fma.rn.f32x2
//                    against h broadcast from SMEM (conflict-free), then a
//                    single STS. Weights live in 100 registers per thread.
//   threads 0..99  : after barrier A, gate math for hidden unit j = tid
//                    (only 4 warps execute this block).
//   threads 0..299 : 3-step-deep xg prefetch pipeline into double-buffered
//                    SMEM stage (1 LDG per step, latency hidden across ~2
//                    steps).
// Two barriers per step. Zero SHFLs. FMA-pipe floor: 250 cyc/step.
// ---------------------------------------------------------------------------
__global__ __launch_bounds__(384, 1) void gru_rec(
    const float* __restrict__ xg,     // [B][S][300] precomputed input gates (+b_ih)
    const float* __restrict__ w_hh,   // [300][100]
    const float* __restrict__ b_hh,   // [300]
    const float* __restrict__ h0,     // [B][100] (this layer's slice)
    float* __restrict__ y)            // [B][S][100]
{
    __shared__ __align__(16) float h_s[2][104];   // row stride 416B (16B-aligned)
    __shared__ float hg_s[304];
    __shared__ float xg_s[2][304];

    const int b   = blockIdx.x;
    const int tid = threadIdx.x;
    const bool mv = (tid < Gq);       // matvec / loader threads

    // full 100-wide weight row, packed as 50 f32x2 pairs (100 registers)
    unsigned long long wp[50];
    float bhh = 0.f;
    if (mv) {
        const float4* wrow = (const float4*)(w_hh + tid * Hq);  // 400B rows, 16B-aligned
#pragma unroll
        for (int q = 0; q < 25; q++) {
            const float4 v = __ldg(wrow + q);
            asm("mov.b64 %0, {%1, %2};" : "=l"(wp[2 * q])     : "f"(v.x), "f"(v.y));
            asm("mov.b64 %0, {%1, %2};" : "=l"(wp[2 * q + 1]) : "f"(v.z), "f"(v.w));
        }
        bhh = b_hh[tid];
    }
    if (tid < Hq) h_s[0][tid] = h0[b * Hq + tid];

    const float* xg_b = xg + (size_t)b * Sq * Gq;
    float*       y_b  = y  + (size_t)b * Sq * Hq;

    // xg pipeline: step 0 staged to SMEM now; steps 1,2 held in registers
    float pA = 0.f, pB = 0.f;
    if (mv) {
        xg_s[0][tid] = xg_b[tid];
        pA = xg_b[Gq + tid];
        pB = xg_b[2 * Gq + tid];
    }
    __syncthreads();

    int cur = 0;
    for (int t = 0; t < Sq; t++) {
        const int tb = t & 1;

        // prefetch xg for step t+3 (consumed ~2 steps / ~1000 cyc from now)
        float pC = 0.f;
        if (mv && t + 3 < Sq)
            pC = xg_b[(size_t)(t + 3) * Gq + tid];

        // full-row matvec: hg[tid] = w_hh[tid,:] . h   (broadcast LDS, no shfl)
        if (mv) {
            const ulonglong2* hp = (const ulonglong2*)h_s[cur];
            unsigned long long a0 = 0ull, a1 = 0ull;
#pragma unroll
            for (int q = 0; q < 25; q++) {
                const ulonglong2 hv = hp[q];       // 16B broadcast (all lanes same addr)
                FMA2(a0, wp[2 * q],     hv.x);
                FMA2(a1, wp[2 * q + 1], hv.y);
            }
            unsigned long long asum;
            asm("add.rn.f32x2 %0, %1, %2;" : "=l"(asum) : "l"(a0), "l"(a1));
            float lo, hi;
            asm("mov.b64 {%0, %1}, %2;" : "=f"(lo), "=f"(hi) : "l"(asum));
            hg_s[tid] = lo + hi + bhh;
        }
        __syncthreads();   // A: hg complete

        // gate math: only threads 0..99 (warps 0-3)
        if (tid < Hq) {
            const float xr = xg_s[tb][tid];
            const float xz = xg_s[tb][Hq + tid];
            const float xn = xg_s[tb][2 * Hq + tid];
            const float hr = hg_s[tid];
            const float hz = hg_s[Hq + tid];
            const float hn = hg_s[2 * Hq + tid];
            const float hprev = h_s[cur][tid];
            const float r  = __fdividef(1.f, 1.f + __expf(-(xr + hr)));
            const float z  = __fdividef(1.f, 1.f + __expf(-(xz + hz)));
            const float na = xn + r * hn;
            const float e  = __expf(-2.f * fabsf(na));
            const float nt = copysignf(__fdividef(1.f - e, 1.f + e), na);
            const float hnew = (1.f - z) * nt + z * hprev;
            h_s[cur ^ 1][tid] = hnew;
            y_b[(size_t)t * Hq + tid] = hnew;
        }

        // stage xg for step t+1 into the other buffer; shift pipeline
        if (mv && t + 1 < Sq)
            xg_s[tb ^ 1][tid] = pA;
        pA = pB; pB = pC;

        cur ^= 1;
        __syncthreads();   // B: h[next] + xg stage complete
    }
}

// ---------------------------------------------------------------------------
// Launch: 5 kernels on the default stream (graph-capturable, no allocs).
// ---------------------------------------------------------------------------
extern "C" void kernel_launch(void* const* d_in, const int* in_sizes, int n_in,
                              void* d_out, int out_size)
{
    (void)in_sizes; (void)n_in; (void)out_size;
    const float* seq     = (const float*)d_in[0];
    const float* h0      = (const float*)d_in[1];   // [2][B][H]
    const float* w_ih_l0 = (const float*)d_in[2];
    const float* w_hh_l0 = (const float*)d_in[3];
    const float* b_ih_l0 = (const float*)d_in[4];
    const float* b_hh_l0 = (const float*)d_in[5];
    const float* w_ih_l1 = (const float*)d_in[6];
    const float* w_hh_l1 = (const float*)d_in[7];
    const float* b_ih_l1 = (const float*)d_in[8];
    const float* b_hh_l1 = (const float*)d_in[9];
    const float* w_out   = (const float*)d_in[10];
    const float* b_out   = (const float*)d_in[11];
    float* out = (float*)d_out;

    float* xgbuf = nullptr;
    float* ybuf  = nullptr;
    cudaGetSymbolAddress((void**)&xgbuf, g_xg);
    cudaGetSymbolAddress((void**)&ybuf,  g_y);

    dim3 g300((Gq + BN - 1) / BN, Mq / BM);   // (3, 1024)
    dim3 gout((OUTq + BN - 1) / BN, Mq / BM); // (1, 1024)

    gemm_bias<<<g300, 256>>>(seq, w_ih_l0, b_ih_l0, xgbuf, Gq, INq);
    gru_rec  <<<Bq, 384>>>(xgbuf, w_hh_l0, b_hh_l0, h0,           ybuf);
    gemm_bias<<<g300, 256>>>(ybuf, w_ih_l1, b_ih_l1, xgbuf, Gq, Hq);
    gru_rec  <<<Bq, 384>>>(xgbuf, w_hh_l1, b_hh_l1, h0 + Bq * Hq, ybuf);
    gemm_bias<<<gout, 256>>>(ybuf, w_out, b_out, out, OUTq, Hq);
}

// round 6
// speedup vs baseline: 1.2976x; 1.2976x over previous
#include <cuda_runtime.h>
#include <cstdint>
#include <cstdio>

// Problem constants
#define Bq   64
#define Sq   2048
#define INq  208
#define Hq   100
#define Gq   300      // 3*H gate rows
#define OUTq 98
#define Mq   (Bq * Sq)   // 131072 rows

// ---------------------------------------------------------------------------
// Scratch (static __device__ arrays — allocation is forbidden)
// ---------------------------------------------------------------------------
__device__ float g_xg[(size_t)Mq * Gq];  // 157 MB: xg0, then reused for xg1
__device__ float g_y [(size_t)Mq * Hq];  //  52 MB: y0, then reused for y1

#define FMA2(c, a, b) \
    asm("fma.rn.f32x2 %0, %1, %2, %0;" : "+l"(c) : "l"(a), "l"(b))

// ---------------------------------------------------------------------------
// GEMM with bias: C[m][n] = bias[n] + sum_k A[m][k] * W[n][k]
// A: M x K row-major, W: N x K row-major (A @ W^T), C: M x N.
// BM=256, BN=64, BK=4, 256 threads, 8x8 microtile (plain FFMA — proven R3
// structure; BN=64 cuts N-direction waste for N=300 from 28% to 6%).
// Requires: M % 256 == 0, K % 4 == 0, K >= 4.
// ---------------------------------------------------------------------------
#define BM 256
#define BN 64
#define BK 4

__global__ __launch_bounds__(256, 2) void gemm_bias(
    const float* __restrict__ A, const float* __restrict__ W,
    const float* __restrict__ bias, float* __restrict__ C,
    int N, int K)
{
    __shared__ float As[BK][BM + 4];
    __shared__ float Ws[BK][BN + 4];

    const int n0  = blockIdx.x * BN;
    const int m0  = blockIdx.y * BM;
    const int tid = threadIdx.x;
    const int tx  = tid & 7;         // n microtile (0..7)
    const int ty  = tid >> 3;        // m microtile (0..31)

    float c[8][8];
#pragma unroll
    for (int i = 0; i < 8; i++)
#pragma unroll
        for (int j = 0; j < 8; j++) c[i][j] = 0.f;

    // Loaders: every thread streams one A row; threads 0..63 also one W row.
    const float* Ap = A + (size_t)(m0 + tid) * K;
    const bool wldr = tid < BN;
    const bool wrow = wldr && (n0 + tid) < N;
    const float* Wp = W + (size_t)(n0 + (wldr ? tid : 0)) * K;

    for (int k0 = 0; k0 < K; k0 += BK) {
        const float4 av = *(const float4*)(Ap + k0);
        const float4 wv = wrow ? *(const float4*)(Wp + k0)
                               : make_float4(0.f, 0.f, 0.f, 0.f);
        __syncthreads();   // protect previous tile's readers
        As[0][tid] = av.x; As[1][tid] = av.y;
        As[2][tid] = av.z; As[3][tid] = av.w;
        if (wldr) {
            Ws[0][tid] = wv.x; Ws[1][tid] = wv.y;
            Ws[2][tid] = wv.z; Ws[3][tid] = wv.w;
        }
        __syncthreads();
#pragma unroll
        for (int k = 0; k < BK; k++) {
            float af[8], bf[8];
            *(float4*)&af[0] = *(const float4*)&As[k][ty * 8];
            *(float4*)&af[4] = *(const float4*)&As[k][ty * 8 + 4];
            *(float4*)&bf[0] = *(const float4*)&Ws[k][tx * 8];
            *(float4*)&bf[4] = *(const float4*)&Ws[k][tx * 8 + 4];
#pragma unroll
            for (int i = 0; i < 8; i++)
#pragma unroll
                for (int j = 0; j < 8; j++) c[i][j] += af[i] * bf[j];
        }
    }

#pragma unroll
    for (int i = 0; i < 8; i++) {
        const size_t m = (size_t)m0 + ty * 8 + i;
#pragma unroll
        for (int j = 0; j < 8; j++) {
            const int n = n0 + tx * 8 + j;
            if (n < N) C[m * N + n] = c[i][j] + bias[n];
        }
    }
}

// ---------------------------------------------------------------------------
// GRU recurrence (round-6 scan).
// One CTA per batch element (64 CTAs), 384 threads (12 warps).
//   threads 0..299 : full gate row g = tid; hg[g] = w_hh[g,:] . h over a
//                    100-wide dot (50 fma.rn.f32x2 in FOUR accumulator
//                    chains -> ~52-cyc dep chain). Weights in 100 regs.
//                    h broadcast from SMEM via LDS.128 (conflict-free).
//   threads 0..99  : gate math for hidden unit j = tid.
// xg arrives via a 4-deep cp.async GMEM->SMEM ring: the load for step t+3
// is issued at the top of step t with NO register involvement; wait_group 2
// at the step end completes a load issued ~2 steps (~800 cyc) earlier.
// Time loop unrolled x2 (compile-time h ping-pong); prefetch row index is
// clamped branchlessly. Two barriers per step, zero shuffles.
// ---------------------------------------------------------------------------
#define RING 4

__device__ __forceinline__ void cp_async4(uint32_t saddr, const float* gptr) {
    asm volatile("cp.async.ca.shared.global [%0], [%1], 4;"
                 :: "r"(saddr), "l"(gptr));
}

struct GruSmem {
    float h[2][104];
    float hg[304];
    float ring[RING][304];
};

__device__ __forceinline__ void gru_step(
    int t, int cur, bool mv, int tid,
    GruSmem* s, uint32_t ring_sa,
    const unsigned long long* wp, float bhh,
    const float* __restrict__ xg_b, float* __restrict__ y_b)
{
    // prefetch xg row for step t+3 into ring slot (t+3)%RING (no registers)
    if (mv) {
        int r = t + 3;
        r = (r < Sq) ? r : (Sq - 1);                    // branchless clamp
        cp_async4(ring_sa + (((t + 3) & (RING - 1)) * 304 + tid) * 4,
                  xg_b + (size_t)r * Gq + tid);
    }
    asm volatile("cp.async.commit_group;" ::: "memory");

    // full-row matvec
    if (mv) {
        const ulonglong2* hp = (const ulonglong2*)s->h[cur];
        unsigned long long a0 = 0ull, a1 = 0ull, a2 = 0ull, a3 = 0ull;
#pragma unroll
        for (int q = 0; q < 25; q++) {
            const ulonglong2 hv = hp[q];                // 16B broadcast
            if (q & 1) { FMA2(a1, wp[2 * q], hv.x); FMA2(a3, wp[2 * q + 1], hv.y); }
            else       { FMA2(a0, wp[2 * q], hv.x); FMA2(a2, wp[2 * q + 1], hv.y); }
        }
        unsigned long long s01, s23, ssum;
        asm("add.rn.f32x2 %0, %1, %2;" : "=l"(s01)  : "l"(a0),  "l"(a1));
        asm("add.rn.f32x2 %0, %1, %2;" : "=l"(s23)  : "l"(a2),  "l"(a3));
        asm("add.rn.f32x2 %0, %1, %2;" : "=l"(ssum) : "l"(s01), "l"(s23));
        float lo, hi;
        asm("mov.b64 {%0, %1}, %2;" : "=f"(lo), "=f"(hi) : "l"(ssum));
        s->hg[tid] = lo + hi + bhh;
    }
    __syncthreads();   // A: hg complete

    // gate math (threads 0..99; ring slot t%RING was completed last step)
    if (tid < Hq) {
        const float* xgp = s->ring[t & (RING - 1)];
        const float xr = xgp[tid], xz = xgp[Hq + tid], xn = xgp[2 * Hq + tid];
        const float hr = s->hg[tid];
        const float hz = s->hg[Hq + tid];
        const float hn = s->hg[2 * Hq + tid];
        const float hprev = s->h[cur][tid];
        const float r  = __fdividef(1.f, 1.f + __expf(-(xr + hr)));
        const float z  = __fdividef(1.f, 1.f + __expf(-(xz + hz)));
        const float na = xn + r * hn;
        const float e  = __expf(-2.f * fabsf(na));
        const float nt = copysignf(__fdividef(1.f - e, 1.f + e), na);
        const float hnew = (1.f - z) * nt + z * hprev;
        s->h[cur ^ 1][tid] = hnew;
        y_b[(size_t)t * Hq + tid] = hnew;
    }

    // complete the cp.async issued 2 steps ago (slot t+1), then publish
    asm volatile("cp.async.wait_group 2;" ::: "memory");
    __syncthreads();   // B: h[next], slot t+1 visible to all
}

__global__ __launch_bounds__(384, 1) void gru_rec(
    const float* __restrict__ xg,     // [B][S][300] precomputed input gates (+b_ih)
    const float* __restrict__ w_hh,   // [300][100]
    const float* __restrict__ b_hh,   // [300]
    const float* __restrict__ h0,     // [B][100] (this layer's slice)
    float* __restrict__ y)            // [B][S][100]
{
    __shared__ __align__(16) GruSmem s;

    const int b   = blockIdx.x;
    const int tid = threadIdx.x;
    const bool mv = (tid < Gq);

    // full 100-wide weight row, packed as 50 f32x2 pairs (100 registers)
    unsigned long long wp[50];
    float bhh = 0.f;
    if (mv) {
        const float4* wrow = (const float4*)(w_hh + tid * Hq);
#pragma unroll
        for (int q = 0; q < 25; q++) {
            const float4 v = __ldg(wrow + q);
            asm("mov.b64 %0, {%1, %2};" : "=l"(wp[2 * q])     : "f"(v.x), "f"(v.y));
            asm("mov.b64 %0, {%1, %2};" : "=l"(wp[2 * q + 1]) : "f"(v.z), "f"(v.w));
        }
        bhh = b_hh[tid];
    }
    if (tid < Hq) s.h[0][tid] = h0[b * Hq + tid];

    const float* xg_b = xg + (size_t)b * Sq * Gq;
    float*       y_b  = y  + (size_t)b * Sq * Hq;

    const uint32_t ring_sa = (uint32_t)__cvta_generic_to_shared(&s.ring[0][0]);

    // prologue: stage rows 0,1,2 into ring slots 0,1,2 (3 commit groups)
#pragma unroll
    for (int p = 0; p < 3; p++) {
        if (mv) cp_async4(ring_sa + (p * 304 + tid) * 4, xg_b + (size_t)p * Gq + tid);
        asm volatile("cp.async.commit_group;" ::: "memory");
    }
    asm volatile("cp.async.wait_group 2;" ::: "memory");   // slot 0 ready
    __syncthreads();

    for (int t = 0; t < Sq; t += 2) {
        gru_step(t,     0, mv, tid, &s, ring_sa, wp, bhh, xg_b, y_b);
        gru_step(t + 1, 1, mv, tid, &s, ring_sa, wp, bhh, xg_b, y_b);
    }
}

// ---------------------------------------------------------------------------
// Launch: 5 kernels on the default stream (graph-capturable, no allocs).
// ---------------------------------------------------------------------------
extern "C" void kernel_launch(void* const* d_in, const int* in_sizes, int n_in,
                              void* d_out, int out_size)
{
    (void)in_sizes; (void)n_in; (void)out_size;
    const float* seq     = (const float*)d_in[0];
    const float* h0      = (const float*)d_in[1];   // [2][B][H]
    const float* w_ih_l0 = (const float*)d_in[2];
    const float* w_hh_l0 = (const float*)d_in[3];
    const float* b_ih_l0 = (const float*)d_in[4];
    const float* b_hh_l0 = (const float*)d_in[5];
    const float* w_ih_l1 = (const float*)d_in[6];
    const float* w_hh_l1 = (const float*)d_in[7];
    const float* b_ih_l1 = (const float*)d_in[8];
    const float* b_hh_l1 = (const float*)d_in[9];
    const float* w_out   = (const float*)d_in[10];
    const float* b_out   = (const float*)d_in[11];
    float* out = (float*)d_out;

    float* xgbuf = nullptr;
    float* ybuf  = nullptr;
    cudaGetSymbolAddress((void**)&xgbuf, g_xg);
    cudaGetSymbolAddress((void**)&ybuf,  g_y);

    dim3 g300((Gq + BN - 1) / BN, Mq / BM);   // (5, 512)
    dim3 gout((OUTq + BN - 1) / BN, Mq / BM); // (2, 512)

    gemm_bias<<<g300, 256>>>(seq, w_ih_l0, b_ih_l0, xgbuf, Gq, INq);
    gru_rec  <<<Bq, 384>>>(xgbuf, w_hh_l0, b_hh_l0, h0,           ybuf);
    gemm_bias<<<g300, 256>>>(ybuf, w_ih_l1, b_ih_l1, xgbuf, Gq, Hq);
    gru_rec  <<<Bq, 384>>>(xgbuf, w_hh_l1, b_hh_l1, h0 + Bq * Hq, ybuf);
    gemm_bias<<<gout, 256>>>(ybuf, w_out, b_out, out, OUTq, Hq);
}

// round 9
// speedup vs baseline: 1.7260x; 1.3301x over previous
#include <cuda_runtime.h>
#include <cstdint>

// Problem constants
#define Bq   64
#define Sq   2048
#define INq  208
#define Hq   100
#define Gq   300      // 3*H gate rows
#define OUTq 98
#define Mq   (Bq * Sq)   // 131072 rows

#define NC   8          // chunks
#define CS   256        // steps per chunk

// ---------------------------------------------------------------------------
// Scratch (static __device__ arrays — allocation is forbidden)
// ---------------------------------------------------------------------------
__device__ float g_xg0[(size_t)Mq * Gq];  // layer-0 input gates (G1 output)
__device__ float g_xg1[(size_t)Mq * Gq];  // layer-1 input gates (inline G2)
__device__ float g_y0 [(size_t)Mq * Hq];  // layer-0 hidden sequence
__device__ float g_y1 [(size_t)Mq * Hq];  // layer-1 hidden sequence
__device__ int   g_fl0[Bq];               // L0 chunks-done per batch
__device__ int   g_fl1[Bq];               // L1 chunks-done per batch
__device__ int   g_jobctr;                // G3 dynamic job counter

#define FMA2(c, a, b) \
    asm("fma.rn.f32x2 %0, %1, %2, %0;" : "+l"(c) : "l"(a), "l"(b))

// ---------------------------------------------------------------------------
// Flag reset (runs first every call — keeps replays deterministic)
// ---------------------------------------------------------------------------
__global__ void zero_flags() {
    const int t = threadIdx.x;
    if (t < Bq) { g_fl0[t] = 0; g_fl1[t] = 0; }
    if (t == 0) g_jobctr = 0;
}

// ---------------------------------------------------------------------------
// G1 GEMM with bias (full M): C[m][n] = bias[n] + sum_k A[m][k]*W[n][k]
// BM=256, BN=64, BK=4, 256 threads, 8x8 microtile (R6-proven).
// ---------------------------------------------------------------------------
#define BM 256
#define BN 64
#define BK 4

__global__ __launch_bounds__(256, 2) void gemm_bias(
    const float* __restrict__ A, const float* __restrict__ W,
    const float* __restrict__ bias, float* __restrict__ C,
    int N, int K)
{
    __shared__ float As[BK][BM + 4];
    __shared__ float Ws[BK][BN + 4];

    const int n0  = blockIdx.x * BN;
    const int m0  = blockIdx.y * BM;
    const int tid = threadIdx.x;
    const int tx  = tid & 7;
    const int ty  = tid >> 3;

    float c[8][8];
#pragma unroll
    for (int i = 0; i < 8; i++)
#pragma unroll
        for (int j = 0; j < 8; j++) c[i][j] = 0.f;

    const float* Ap = A + (size_t)(m0 + tid) * K;
    const bool wldr = tid < BN;
    const bool wrow = wldr && (n0 + tid) < N;
    const float* Wp = W + (size_t)(n0 + (wldr ? tid : 0)) * K;

    for (int k0 = 0; k0 < K; k0 += BK) {
        const float4 av = *(const float4*)(Ap + k0);
        const float4 wv = wrow ? *(const float4*)(Wp + k0)
                               : make_float4(0.f, 0.f, 0.f, 0.f);
        __syncthreads();
        As[0][tid] = av.x; As[1][tid] = av.y;
        As[2][tid] = av.z; As[3][tid] = av.w;
        if (wldr) {
            Ws[0][tid] = wv.x; Ws[1][tid] = wv.y;
            Ws[2][tid] = wv.z; Ws[3][tid] = wv.w;
        }
        __syncthreads();
#pragma unroll
        for (int k = 0; k < BK; k++) {
            float af[8], bf[8];
            *(float4*)&af[0] = *(const float4*)&As[k][ty * 8];
            *(float4*)&af[4] = *(const float4*)&As[k][ty * 8 + 4];
            *(float4*)&bf[0] = *(const float4*)&Ws[k][tx * 8];
            *(float4*)&bf[4] = *(const float4*)&Ws[k][tx * 8 + 4];
#pragma unroll
            for (int i = 0; i < 8; i++)
#pragma unroll
                for (int j = 0; j < 8; j++) c[i][j] += af[i] * bf[j];
        }
    }

#pragma unroll
    for (int i = 0; i < 8; i++) {
        const size_t m = (size_t)m0 + ty * 8 + i;
#pragma unroll
        for (int j = 0; j < 8; j++) {
            const int n = n0 + tx * 8 + j;
            if (n < N) C[m * N + n] = c[i][j] + bias[n];
        }
    }
}

// ---------------------------------------------------------------------------
// Shared helpers for the persistent pipeline kernel
// ---------------------------------------------------------------------------
#define RING 4

__device__ __forceinline__ void cp_async4(uint32_t saddr, const float* gptr) {
    asm volatile("cp.async.ca.shared.global [%0], [%1], 4;"
                 :: "r"(saddr), "l"(gptr));
}
__device__ __forceinline__ void cp_async16(uint32_t saddr, const void* gptr) {
    asm volatile("cp.async.cg.shared.global [%0], [%1], 16;"
                 :: "r"(saddr), "l"(gptr));
}
#define CP_COMMIT()  asm volatile("cp.async.commit_group;" ::: "memory")
#define CP_WAIT(n)   asm volatile("cp.async.wait_group %0;" :: "n"(n) : "memory")

struct GruSmem {
    float h[2][104];
    float hg[304];
    float ring[RING][304];
};

// load a 100-float row (16B aligned) into 50 packed f32x2 register pairs
__device__ __forceinline__ void load_row100(unsigned long long* wp,
                                            const float* row) {
    const float4* r4 = (const float4*)row;
#pragma unroll
    for (int q = 0; q < 25; q++) {
        const float4 v = __ldg(r4 + q);
        asm("mov.b64 %0, {%1, %2};" : "=l"(wp[2 * q])     : "f"(v.x), "f"(v.y));
        asm("mov.b64 %0, {%1, %2};" : "=l"(wp[2 * q + 1]) : "f"(v.z), "f"(v.w));
    }
}

// 100-wide dot: packed weights vs 16B-aligned SMEM vector (broadcast reads)
__device__ __forceinline__ float dot100(const unsigned long long* wp,
                                        const float* vec) {
    const ulonglong2* hp = (const ulonglong2*)vec;
    unsigned long long a0 = 0ull, a1 = 0ull, a2 = 0ull, a3 = 0ull;
#pragma unroll
    for (int q = 0; q < 25; q++) {
        const ulonglong2 hv = hp[q];
        if (q & 1) { FMA2(a1, wp[2 * q], hv.x); FMA2(a3, wp[2 * q + 1], hv.y); }
        else       { FMA2(a0, wp[2 * q], hv.x); FMA2(a2, wp[2 * q + 1], hv.y); }
    }
    unsigned long long s01, s23, ssum;
    asm("add.rn.f32x2 %0, %1, %2;" : "=l"(s01)  : "l"(a0),  "l"(a1));
    asm("add.rn.f32x2 %0, %1, %2;" : "=l"(s23)  : "l"(a2),  "l"(a3));
    asm("add.rn.f32x2 %0, %1, %2;" : "=l"(ssum) : "l"(s01), "l"(s23));
    float lo, hi;
    asm("mov.b64 {%0, %1}, %2;" : "=f"(lo), "=f"(hi) : "l"(ssum));
    return lo + hi;
}

// one GRU timestep (R6-proven structure)
__device__ __forceinline__ void gru_step(
    int t, int cur, bool mv, int tid,
    GruSmem* s, uint32_t ring_sa,
    const unsigned long long* wp, float bhh,
    const float* __restrict__ xg_b, float* __restrict__ y_b)
{
    if (mv) {                                   // prefetch xg row t+3
        int r = t + 3;
        r = (r < Sq) ? r : (Sq - 1);
        cp_async4(ring_sa + (((t + 3) & (RING - 1)) * 304 + tid) * 4,
                  xg_b + (size_t)r * Gq + tid);
    }
    CP_COMMIT();

    if (mv) s->hg[tid] = dot100(wp, s->h[cur]) + bhh;
    __syncthreads();                            // A: hg complete

    if (tid < Hq) {
        const float* xgp = s->ring[t & (RING - 1)];
        const float xr = xgp[tid], xz = xgp[Hq + tid], xn = xgp[2 * Hq + tid];
        const float hr = s->hg[tid];
        const float hz = s->hg[Hq + tid];
        const float hn = s->hg[2 * Hq + tid];
        const float hprev = s->h[cur][tid];
        const float r  = __fdividef(1.f, 1.f + __expf(-(xr + hr)));
        const float z  = __fdividef(1.f, 1.f + __expf(-(xz + hz)));
        const float na = xn + r * hn;
        const float e  = __expf(-2.f * fabsf(na));
        const float nt = copysignf(__fdividef(1.f - e, 1.f + e), na);
        const float hnew = (1.f - z) * nt + z * hprev;
        s->h[cur ^ 1][tid] = hnew;
        y_b[(size_t)t * Hq + tid] = hnew;
    }
    CP_WAIT(2);                                 // ring slot t+1 landed
    __syncthreads();                            // B: publish
}

__device__ __forceinline__ void wait_flag(volatile int* f, int target, int tid) {
    if (tid == 0) {
        while (*f < target) __nanosleep(128);
    }
    __syncthreads();
    __threadfence();                            // acquire
}

// ---------------------------------------------------------------------------
// Persistent pipeline kernel. grid = 144 CTAs x 384 threads, occ forced to
// 1/SM via 116KB dynamic smem -> all CTAs co-resident (no spin deadlock).
//   CTA 0..63    : L0 scan for batch b, flags fl0[b] per 256-step chunk
//   CTA 64..127  : L1: per chunk wait fl0 -> stage y0 -> inline G2 (xg1)
//                  -> scan chunk -> flag fl1[b]
//   CTA 128..143 : G3 workers (dynamic job queue); finished scan CTAs join
// ---------------------------------------------------------------------------
__global__ __launch_bounds__(384, 1) void pipeline_kernel(
    const float* __restrict__ w_hh_l0, const float* __restrict__ b_hh_l0,
    const float* __restrict__ w_ih_l1, const float* __restrict__ b_ih_l1,
    const float* __restrict__ w_hh_l1, const float* __restrict__ b_hh_l1,
    const float* __restrict__ w_out,   const float* __restrict__ b_out,
    const float* __restrict__ h0,      float* __restrict__ out)
{
    extern __shared__ float stage[];            // CS*Hq = 25600 floats used
    __shared__ __align__(16) GruSmem s;
    __shared__ int js;

    const int tid  = threadIdx.x;
    const int role = blockIdx.x;
    const bool mv  = (tid < Gq);
    const uint32_t ring_sa  = (uint32_t)__cvta_generic_to_shared(&s.ring[0][0]);
    const uint32_t stage_sa = (uint32_t)__cvta_generic_to_shared(stage);

    unsigned long long wp[50];

    if (role < Bq) {
        // ---------------- L0 scan ----------------
        const int b = role;
        float bhh = 0.f;
        if (mv) { load_row100(wp, w_hh_l0 + tid * Hq); bhh = b_hh_l0[tid]; }
        if (tid < Hq) s.h[0][tid] = h0[b * Hq + tid];
        const float* xg_b = g_xg0 + (size_t)b * Sq * Gq;
        float*       y_b  = g_y0  + (size_t)b * Sq * Hq;

#pragma unroll
        for (int p = 0; p < 3; p++) {
            if (mv) cp_async4(ring_sa + (p * 304 + tid) * 4,
                              xg_b + (size_t)p * Gq + tid);
            CP_COMMIT();
        }
        CP_WAIT(2);
        __syncthreads();

        for (int t = 0; t < Sq; t += 2) {
            gru_step(t,     0, mv, tid, &s, ring_sa, wp, bhh, xg_b, y_b);
            gru_step(t + 1, 1, mv, tid, &s, ring_sa, wp, bhh, xg_b, y_b);
            if (((t + 2) & (CS - 1)) == 0) {    // chunk boundary: release
                __threadfence();
                __syncthreads();
                if (tid == 0) atomicExch(g_fl0 + b, (t + 2) >> 8);
            }
        }
        // fall through to G3 pool
    } else if (role < 2 * Bq) {
        // ---------------- L1: inline-G2 + scan ----------------
        const int b = role - Bq;
        const float* y0_b  = g_y0  + (size_t)b * Sq * Hq;
        float*       xg1_b = g_xg1 + (size_t)b * Sq * Gq;
        float*       y1_b  = g_y1  + (size_t)b * Sq * Hq;
        float bval = 0.f;
        if (tid < Hq) s.h[0][tid] = h0[Bq * Hq + b * Hq + tid];

        for (int c = 0; c < NC; c++) {
            const int t0 = c * CS;
            wait_flag(g_fl0 + b, c + 1, tid);

            // stage y0 chunk into SMEM (cg: bypass L1, read L2-fresh data)
            {
                const float4* src = (const float4*)(y0_b + (size_t)t0 * Hq);
                for (int i = tid; i < CS * Hq / 4; i += 384)
                    cp_async16(stage_sa + i * 16, src + i);
                CP_COMMIT();
                CP_WAIT(0);
                __syncthreads();
            }

            // inline G2: xg1 row tid for all 256 steps of the chunk
            if (mv) {
                load_row100(wp, w_ih_l1 + tid * Hq);
                bval = b_ih_l1[tid];
                float* dst = xg1_b + (size_t)t0 * Gq + tid;
#pragma unroll 2
                for (int t = 0; t < CS; t++)
                    dst[(size_t)t * Gq] = dot100(wp, stage + t * Hq) + bval;
            }
            __threadfence();
            __syncthreads();

            // scan the chunk
            if (mv) { load_row100(wp, w_hh_l1 + tid * Hq); bval = b_hh_l1[tid]; }
#pragma unroll
            for (int p = 0; p < 3; p++) {
                if (mv) cp_async4(ring_sa + (((t0 + p) & (RING - 1)) * 304 + tid) * 4,
                                  xg1_b + (size_t)(t0 + p) * Gq + tid);
                CP_COMMIT();
            }
            CP_WAIT(2);
            __syncthreads();

            for (int t = t0; t < t0 + CS; t += 2) {
                gru_step(t,     0, mv, tid, &s, ring_sa, wp, bval, xg1_b, y1_b);
                gru_step(t + 1, 1, mv, tid, &s, ring_sa, wp, bval, xg1_b, y1_b);
            }
            __threadfence();
            __syncthreads();
            if (tid == 0) atomicExch(g_fl1 + b, c + 1);
        }
        // fall through to G3 pool
    }

    // ---------------- G3 pool: out = y1 @ w_out^T + b_out ----------------
    {
        const int n  = tid & 127;
        const int tq = tid >> 7;                // 0..2
        const bool act = (n < OUTq) && (tq < 3);
        float bo = 0.f;
        if (act) { load_row100(wp, w_out + n * Hq); bo = b_out[n]; }

        for (;;) {
            if (tid == 0) js = atomicAdd(&g_jobctr, 1);
            __syncthreads();
            const int j = js;
            __syncthreads();                    // js stable before next write
            if (j >= Bq * NC) break;
            const int b = j & (Bq - 1);
            const int c = j >> 6;

            wait_flag(g_fl1 + b, c + 1, tid);

            const float4* src = (const float4*)(g_y1 +
                                ((size_t)b * Sq + c * CS) * Hq);
            for (int i = tid; i < CS * Hq / 4; i += 384)
                cp_async16(stage_sa + i * 16, src + i);
            CP_COMMIT();
            CP_WAIT(0);
            __syncthreads();

            if (act) {
                float* ob = out + ((size_t)b * Sq + c * CS) * OUTq;
                for (int t = tq; t < CS; t += 3)
                    ob[(size_t)t * OUTq + n] = dot100(wp, stage + t * Hq) + bo;
            }
            __syncthreads();                    // protect stage (WAR)
        }
    }
}

// ---------------------------------------------------------------------------
// Launch: zero_flags -> G1 (full chip) -> persistent pipeline. One stream,
// graph-capturable, no allocations.
// ---------------------------------------------------------------------------
extern "C" void kernel_launch(void* const* d_in, const int* in_sizes, int n_in,
                              void* d_out, int out_size)
{
    (void)in_sizes; (void)n_in; (void)out_size;
    const float* seq     = (const float*)d_in[0];
    const float* h0      = (const float*)d_in[1];   // [2][B][H]
    const float* w_ih_l0 = (const float*)d_in[2];
    const float* w_hh_l0 = (const float*)d_in[3];
    const float* b_ih_l0 = (const float*)d_in[4];
    const float* b_hh_l0 = (const float*)d_in[5];
    const float* w_ih_l1 = (const float*)d_in[6];
    const float* w_hh_l1 = (const float*)d_in[7];
    const float* b_ih_l1 = (const float*)d_in[8];
    const float* b_hh_l1 = (const float*)d_in[9];
    const float* w_out   = (const float*)d_in[10];
    const float* b_out   = (const float*)d_in[11];
    float* out = (float*)d_out;

    float* xg0 = nullptr;
    cudaGetSymbolAddress((void**)&xg0, g_xg0);

    // occ=1 forcing: dynamic smem > half the 227KB SM budget
    const int STAGE_BYTES = 118784;   // 116 KB (25600*4 = 102400 used)
    cudaFuncSetAttribute(pipeline_kernel,
                         cudaFuncAttributeMaxDynamicSharedMemorySize,
                         STAGE_BYTES);

    zero_flags<<<1, 64>>>();

    dim3 g1((Gq + BN - 1) / BN, Mq / BM);   // (5, 512)
    gemm_bias<<<g1, 256>>>(seq, w_ih_l0, b_ih_l0, xg0, Gq, INq);

    pipeline_kernel<<<144, 384, STAGE_BYTES>>>(
        w_hh_l0, b_hh_l0,
        w_ih_l1, b_ih_l1, w_hh_l1, b_hh_l1,
        w_out, b_out, h0, out);
}

// round 10
// speedup vs baseline: 1.7530x; 1.0157x over previous
#include <cuda_runtime.h>
#include <cstdint>

// Problem constants
#define Bq   64
#define Sq   2048
#define INq  208
#define Hq   100
#define Gq   300      // 3*H gate rows
#define OUTq 98
#define Mq   (Bq * Sq)   // 131072 rows

#define SUB  64         // L0->L1 handoff granularity (steps)
#define NSUB (Sq / SUB) // 32

// ---------------------------------------------------------------------------
// Scratch (static __device__ arrays — allocation is forbidden)
// ---------------------------------------------------------------------------
__device__ float g_xg0[(size_t)Mq * Gq];  // layer-0 input gates (G1 output)
__device__ float g_y0 [(size_t)Mq * Hq];  // layer-0 hidden sequence
__device__ float g_y1 [(size_t)Mq * Hq];  // layer-1 hidden sequence
__device__ int   g_fl0[Bq];               // L0 sub-blocks done per batch
__device__ int   g_fl1[Bq];               // L1 sub-blocks done per batch
__device__ int   g_jobctr;                // G3 dynamic job counter

#define FMA2(c, a, b) \
    asm("fma.rn.f32x2 %0, %1, %2, %0;" : "+l"(c) : "l"(a), "l"(b))

// ---------------------------------------------------------------------------
// G1 GEMM with bias (full M): C[m][n] = bias[n] + sum_k A[m][k]*W[n][k]
// BM=256, BN=64, BK=4, 256 threads, 8x8 microtile (R6-proven).
// Block (0,0) also clears the pipeline flags (runs before the pipeline).
// ---------------------------------------------------------------------------
#define BM 256
#define BN 64
#define BK 4

__global__ __launch_bounds__(256, 2) void gemm_bias(
    const float* __restrict__ A, const float* __restrict__ W,
    const float* __restrict__ bias, float* __restrict__ C,
    int N, int K)
{
    __shared__ float As[BK][BM + 4];
    __shared__ float Ws[BK][BN + 4];

    const int n0  = blockIdx.x * BN;
    const int m0  = blockIdx.y * BM;
    const int tid = threadIdx.x;
    const int tx  = tid & 7;
    const int ty  = tid >> 3;

    if (blockIdx.x == 0 && blockIdx.y == 0) {      // flag reset
        if (tid < Bq) { g_fl0[tid] = 0; g_fl1[tid] = 0; }
        if (tid == Bq) g_jobctr = 0;
    }

    float c[8][8];
#pragma unroll
    for (int i = 0; i < 8; i++)
#pragma unroll
        for (int j = 0; j < 8; j++) c[i][j] = 0.f;

    const float* Ap = A + (size_t)(m0 + tid) * K;
    const bool wldr = tid < BN;
    const bool wrow = wldr && (n0 + tid) < N;
    const float* Wp = W + (size_t)(n0 + (wldr ? tid : 0)) * K;

    for (int k0 = 0; k0 < K; k0 += BK) {
        const float4 av = *(const float4*)(Ap + k0);
        const float4 wv = wrow ? *(const float4*)(Wp + k0)
                               : make_float4(0.f, 0.f, 0.f, 0.f);
        __syncthreads();
        As[0][tid] = av.x; As[1][tid] = av.y;
        As[2][tid] = av.z; As[3][tid] = av.w;
        if (wldr) {
            Ws[0][tid] = wv.x; Ws[1][tid] = wv.y;
            Ws[2][tid] = wv.z; Ws[3][tid] = wv.w;
        }
        __syncthreads();
#pragma unroll
        for (int k = 0; k < BK; k++) {
            float af[8], bf[8];
            *(float4*)&af[0] = *(const float4*)&As[k][ty * 8];
            *(float4*)&af[4] = *(const float4*)&As[k][ty * 8 + 4];
            *(float4*)&bf[0] = *(const float4*)&Ws[k][tx * 8];
            *(float4*)&bf[4] = *(const float4*)&Ws[k][tx * 8 + 4];
#pragma unroll
            for (int i = 0; i < 8; i++)
#pragma unroll
                for (int j = 0; j < 8; j++) c[i][j] += af[i] * bf[j];
        }
    }

#pragma unroll
    for (int i = 0; i < 8; i++) {
        const size_t m = (size_t)m0 + ty * 8 + i;
#pragma unroll
        for (int j = 0; j < 8; j++) {
            const int n = n0 + tx * 8 + j;
            if (n < N) C[m * N + n] = c[i][j] + bias[n];
        }
    }
}

// ---------------------------------------------------------------------------
// Persistent pipeline helpers
// ---------------------------------------------------------------------------
__device__ __forceinline__ void cp_async4(uint32_t saddr, const float* gptr) {
    asm volatile("cp.async.ca.shared.global [%0], [%1], 4;"
                 :: "r"(saddr), "l"(gptr));
}
__device__ __forceinline__ void cp_async16(uint32_t saddr, const void* gptr) {
    asm volatile("cp.async.cg.shared.global [%0], [%1], 16;"
                 :: "r"(saddr), "l"(gptr));
}
#define CP_COMMIT()  asm volatile("cp.async.commit_group;" ::: "memory")
#define CP_WAIT(n)   asm volatile("cp.async.wait_group %0;" :: "n"(n) : "memory")

// All-padded SMEM: every array indexable by all 384 threads -> no guards.
struct GruSmem {
    float h[2][128];        // units 0..99 real, 100..127 pad
    float hg[384];          // rows 0..299 real, rest pad
    float ring[4][384];     // L0 xg staging ring (rows of 384)
};

// load a 100-float row (16B aligned) into 50 packed f32x2 register pairs
__device__ __forceinline__ void load_row100(unsigned long long* wp,
                                            const float* row) {
    const float4* r4 = (const float4*)row;
#pragma unroll
    for (int q = 0; q < 25; q++) {
        const float4 v = __ldg(r4 + q);
        asm("mov.b64 %0, {%1, %2};" : "=l"(wp[2 * q])     : "f"(v.x), "f"(v.y));
        asm("mov.b64 %0, {%1, %2};" : "=l"(wp[2 * q + 1]) : "f"(v.z), "f"(v.w));
    }
}

// 100-wide dot: packed weights vs 16B-aligned SMEM vector (broadcast reads)
__device__ __forceinline__ float dot100(const unsigned long long* wp,
                                        const float* vec) {
    const ulonglong2* hp = (const ulonglong2*)vec;
    unsigned long long a0 = 0ull, a1 = 0ull, a2 = 0ull, a3 = 0ull;
#pragma unroll
    for (int q = 0; q < 25; q++) {
        const ulonglong2 hv = hp[q];
        if (q & 1) { FMA2(a1, wp[2 * q], hv.x); FMA2(a3, wp[2 * q + 1], hv.y); }
        else       { FMA2(a0, wp[2 * q], hv.x); FMA2(a2, wp[2 * q + 1], hv.y); }
    }
    unsigned long long s01, s23, ssum;
    asm("add.rn.f32x2 %0, %1, %2;" : "=l"(s01)  : "l"(a0),  "l"(a1));
    asm("add.rn.f32x2 %0, %1, %2;" : "=l"(s23)  : "l"(a2),  "l"(a3));
    asm("add.rn.f32x2 %0, %1, %2;" : "=l"(ssum) : "l"(s01), "l"(s23));
    float lo, hi;
    asm("mov.b64 {%0, %1}, %2;" : "=f"(lo), "=f"(hi) : "l"(ssum));
    return lo + hi;
}

// One GRU timestep, fully uniform across all 384 threads (no BSSY regions).
// RING_XG: L0 streams xg from gmem via the cp.async ring; L1 reads it from
// the SMEM xg_sub block written by inline-G2 (xg_src = that block).
template<bool RING_XG>
__device__ __forceinline__ void gru_step(
    int t, int cur, int tid, int jc,
    GruSmem* s, uint32_t ring_sa,
    const unsigned long long* wp, float bhh,
    const float* __restrict__ xg_src,   // L0: gmem batch base; L1: smem block
    float* __restrict__ y_b)
{
    if (RING_XG) {
        int r = t + 3; r = (r < Sq) ? r : (Sq - 1);
        cp_async4(ring_sa + (((t + 3) & 3) * 384 + tid) * 4,
                  xg_src + (size_t)r * Gq + min(tid, Gq - 1));
        CP_COMMIT();
    }

    s->hg[tid] = dot100(wp, s->h[cur]) + bhh;    // all 384 threads, uniform
    __syncthreads();                             // A: hg complete

    if (tid < 128) {                             // warp-uniform (warps 0..3)
        const float* xgp = RING_XG ? &s->ring[t & 3][0]
                                   : (xg_src + (t & (SUB - 1)) * 304);
        const float xr = xgp[jc], xz = xgp[Hq + jc], xn = xgp[2 * Hq + jc];
        const float hr = s->hg[jc];
        const float hz = s->hg[Hq + jc];
        const float hn = s->hg[2 * Hq + jc];
        const float hprev = s->h[cur][jc];
        const float r  = __fdividef(1.f, 1.f + __expf(-(xr + hr)));
        const float z  = __fdividef(1.f, 1.f + __expf(-(xz + hz)));
        const float na = xn + r * hn;
        const float e  = __expf(-2.f * fabsf(na));
        const float nt = copysignf(__fdividef(1.f - e, 1.f + e), na);
        const float hnew = (1.f - z) * nt + z * hprev;
        s->h[cur ^ 1][tid] = hnew;               // pads write pad region
        if (tid < Hq) y_b[(size_t)t * Hq + tid] = hnew;   // predicated STG
    }
    if (RING_XG) CP_WAIT(2);                     // ring slot t+1 landed
    __syncthreads();                             // B: publish
}

__device__ __forceinline__ void wait_flag(volatile int* f, int target, int tid) {
    if (tid == 0) {
        while (*f < target) __nanosleep(128);
    }
    __syncthreads();
    __threadfence();                             // acquire
}

// ---------------------------------------------------------------------------
// Persistent pipeline kernel: 144 CTAs x 384 threads (injective CTA->SM map
// for grid<=148 => all co-resident; spin-waits safe).
//   CTA 0..63    : L0 scan (xg0 from gmem ring), flag fl0 per 64 steps
//   CTA 64..127  : L1: per 64-step sub: wait fl0 -> stage y0 -> inline G2
//                  into SMEM -> scan -> flag fl1
//   CTA 128..143 : G3 pool from the start; scan CTAs join when done
// Dynamic SMEM layout (103424 B):
//   L1: ystage[64*100] floats | xg_sub[64][304] floats
//   G3: y1 stage[128*100] floats (reuses the same region)
// ---------------------------------------------------------------------------
__global__ __launch_bounds__(384, 1) void pipeline_kernel(
    const float* __restrict__ w_hh_l0, const float* __restrict__ b_hh_l0,
    const float* __restrict__ w_ih_l1, const float* __restrict__ b_ih_l1,
    const float* __restrict__ w_hh_l1, const float* __restrict__ b_hh_l1,
    const float* __restrict__ w_out,   const float* __restrict__ b_out,
    const float* __restrict__ h0,      float* __restrict__ out)
{
    extern __shared__ __align__(16) float dyn[];
    __shared__ __align__(16) GruSmem s;
    __shared__ int js;

    const int tid  = threadIdx.x;
    const int role = blockIdx.x;
    const int wr   = min(tid, Gq - 1);           // clamped gate-row index
    const int jc   = min(tid, Hq - 1);           // clamped hidden-unit index
    const uint32_t ring_sa = (uint32_t)__cvta_generic_to_shared(&s.ring[0][0]);
    const uint32_t dyn_sa  = (uint32_t)__cvta_generic_to_shared(dyn);

    unsigned long long wp[50];

    if (role < Bq) {
        // ---------------- L0 scan ----------------
        const int b = role;
        load_row100(wp, w_hh_l0 + wr * Hq);
        const float bhh = b_hh_l0[wr];
        if (tid < Hq) s.h[0][tid] = h0[b * Hq + tid];
        const float* xg_b = g_xg0 + (size_t)b * Sq * Gq;
        float*       y_b  = g_y0  + (size_t)b * Sq * Hq;

#pragma unroll
        for (int p = 0; p < 3; p++) {            // stage rows 0..2
            cp_async4(ring_sa + (p * 384 + tid) * 4,
                      xg_b + (size_t)p * Gq + wr);
            CP_COMMIT();
        }
        CP_WAIT(2);
        __syncthreads();

        for (int t = 0; t < Sq; t += 2) {
            gru_step<true>(t,     0, tid, jc, &s, ring_sa, wp, bhh, xg_b, y_b);
            gru_step<true>(t + 1, 1, tid, jc, &s, ring_sa, wp, bhh, xg_b, y_b);
            if (((t + 2) & (SUB - 1)) == 0) {    // release a sub-block
                __threadfence();
                __syncthreads();
                if (tid == 0) atomicExch(g_fl0 + b, (t + 2) / SUB);
            }
        }
        // falls through to G3 pool
    } else if (role < 2 * Bq) {
        // ---------------- L1: stage + inline-G2 + scan, per sub ----------------
        const int b = role - Bq;
        const float* y0_b = g_y0 + (size_t)b * Sq * Hq;
        float*       y1_b = g_y1 + (size_t)b * Sq * Hq;
        float* ystage = dyn;                     // [SUB * Hq]
        float* xg_sub = dyn + SUB * Hq;          // [SUB][304]
        const int col = min(tid, 303);
        if (tid < Hq) s.h[0][tid] = h0[Bq * Hq + b * Hq + tid];
        __syncthreads();

        for (int sub = 0; sub < NSUB; sub++) {
            const int t0 = sub * SUB;
            wait_flag(g_fl0 + b, sub + 1, tid);

            // stage y0 sub-block (cg: fresh-from-L2 path)
            {
                const float4* src = (const float4*)(y0_b + (size_t)t0 * Hq);
                for (int i = tid; i < SUB * Hq / 4; i += 384)
                    cp_async16(dyn_sa + i * 16, src + i);
                CP_COMMIT();
                CP_WAIT(0);
                __syncthreads();
            }

            // inline G2 -> SMEM xg_sub (pads write duplicate of row 299: benign)
            load_row100(wp, w_ih_l1 + wr * Hq);
            const float bih = b_ih_l1[wr];
#pragma unroll 2
            for (int tt = 0; tt < SUB; tt++)
                xg_sub[tt * 304 + col] = dot100(wp, ystage + tt * Hq) + bih;
            __syncthreads();

            // scan the sub-block
            load_row100(wp, w_hh_l1 + wr * Hq);
            const float bhh = b_hh_l1[wr];
            for (int t = t0; t < t0 + SUB; t += 2) {
                gru_step<false>(t,     0, tid, jc, &s, ring_sa, wp, bhh,
                                xg_sub, y1_b);
                gru_step<false>(t + 1, 1, tid, jc, &s, ring_sa, wp, bhh,
                                xg_sub, y1_b);
            }
            __threadfence();
            __syncthreads();
            if (tid == 0) atomicExch(g_fl1 + b, sub + 1);
        }
        // falls through to G3 pool
    }

    // ---------------- G3 pool: out = y1 @ w_out^T + b_out ----------------
    {
        const int nidx = tid & 127;
        const int tq   = tid >> 7;               // 0..2
        const int nr   = min(nidx, OUTq - 1);
        load_row100(wp, w_out + nr * Hq);
        const float bo = b_out[nr];

        for (;;) {
            if (tid == 0) js = atomicAdd(&g_jobctr, 1);
            __syncthreads();
            const int j = js;
            __syncthreads();                     // js stable before next write
            if (j >= Bq * 16) break;             // 1024 jobs of 128 steps
            const int b   = j & (Bq - 1);
            const int blk = j >> 6;              // 0..15

            wait_flag(g_fl1 + b, 2 * blk + 2, tid);

            const float4* src = (const float4*)(g_y1 +
                                ((size_t)b * Sq + blk * 128) * Hq);
            for (int i = tid; i < 128 * Hq / 4; i += 384)
                cp_async16(dyn_sa + i * 16, src + i);
            CP_COMMIT();
            CP_WAIT(0);
            __syncthreads();

            if (nidx < OUTq) {
                float* ob = out + ((size_t)b * Sq + blk * 128) * OUTq;
                for (int tt = tq; tt < 128; tt += 3)
                    ob[(size_t)tt * OUTq + nidx] = dot100(wp, dyn + tt * Hq) + bo;
            }
            __syncthreads();                     // protect stage (WAR)
        }
    }
}

// ---------------------------------------------------------------------------
// Launch: G1 (full chip, also clears flags) -> persistent pipeline.
// One stream, graph-capturable, no allocations.
// ---------------------------------------------------------------------------
extern "C" void kernel_launch(void* const* d_in, const int* in_sizes, int n_in,
                              void* d_out, int out_size)
{
    (void)in_sizes; (void)n_in; (void)out_size;
    const float* seq     = (const float*)d_in[0];
    const float* h0      = (const float*)d_in[1];   // [2][B][H]
    const float* w_ih_l0 = (const float*)d_in[2];
    const float* w_hh_l0 = (const float*)d_in[3];
    const float* b_ih_l0 = (const float*)d_in[4];
    const float* b_hh_l0 = (const float*)d_in[5];
    const float* w_ih_l1 = (const float*)d_in[6];
    const float* w_hh_l1 = (const float*)d_in[7];
    const float* b_ih_l1 = (const float*)d_in[8];
    const float* b_hh_l1 = (const float*)d_in[9];
    const float* w_out   = (const float*)d_in[10];
    const float* b_out   = (const float*)d_in[11];
    float* out = (float*)d_out;

    float* xg0 = nullptr;
    cudaGetSymbolAddress((void**)&xg0, g_xg0);

    const int DYN_BYTES = (SUB * Hq + SUB * 304) * 4;   // 103424
    cudaFuncSetAttribute(pipeline_kernel,
                         cudaFuncAttributeMaxDynamicSharedMemorySize,
                         DYN_BYTES);

    dim3 g1((Gq + BN - 1) / BN, Mq / BM);   // (5, 512)
    gemm_bias<<<g1, 256>>>(seq, w_ih_l0, b_ih_l0, xg0, Gq, INq);

    pipeline_kernel<<<144, 384, DYN_BYTES>>>(
        w_hh_l0, b_hh_l0,
        w_ih_l1, b_ih_l1, w_hh_l1, b_hh_l1,
        w_out, b_out, h0, out);
}

// round 11
// speedup vs baseline: 1.8024x; 1.0281x over previous
#include <cuda_runtime.h>
#include <cstdint>

// Problem constants
#define Bq   64
#define Sq   2048
#define INq  208
#define Hq   100
#define Gq   300      // 3*H gate rows
#define OUTq 98
#define Mq   (Bq * Sq)   // 131072 rows

#define SUB   64          // handoff granularity (steps)
#define NSUB  (Sq / SUB)  // 32
#define NJOB2 (Bq * NSUB) // 2048 G2 jobs
#define XGP   304         // padded xg1 row stride (floats, 16B-aligned)

// ---------------------------------------------------------------------------
// Scratch (static __device__ arrays — allocation is forbidden)
// ---------------------------------------------------------------------------
__device__ float g_xg0 [(size_t)Mq * Gq];   // layer-0 input gates (G1 out)
__device__ float g_xg1p[(size_t)Mq * XGP];  // layer-1 input gates, padded rows
__device__ float g_y0  [(size_t)Mq * Hq];   // layer-0 hidden sequence
__device__ float g_y1  [(size_t)Mq * Hq];   // layer-1 hidden sequence
__device__ int   g_fl0[Bq];                 // L0 sub-blocks done per batch
__device__ int   g_fl1[Bq];                 // L1 sub-blocks done per batch
__device__ int   g_fl2[NJOB2];              // per-job xg1 ready
__device__ int   g_claim[NJOB2];            // 0=free 1=worker 2=L1-inline
__device__ int   g_jobctr;                  // G3 job counter
__device__ int   g_g2ctr;                   // G2 worker job counter

#define FMA2(c, a, b) \
    asm("fma.rn.f32x2 %0, %1, %2, %0;" : "+l"(c) : "l"(a), "l"(b))

__device__ __forceinline__ void cp_async4(uint32_t saddr, const float* gptr) {
    asm volatile("cp.async.ca.shared.global [%0], [%1], 4;"
                 :: "r"(saddr), "l"(gptr));
}
__device__ __forceinline__ void cp_async16(uint32_t saddr, const void* gptr) {
    asm volatile("cp.async.cg.shared.global [%0], [%1], 16;"
                 :: "r"(saddr), "l"(gptr));
}
#define CP_COMMIT()  asm volatile("cp.async.commit_group;" ::: "memory")
#define CP_WAIT(n)   asm volatile("cp.async.wait_group %0;" :: "n"(n) : "memory")

// ---------------------------------------------------------------------------
// Packed-dot helpers: weights live in registers as f32x2 pairs; the vector
// operand is a 16B-aligned SMEM broadcast (conflict-free LDS.128).
// ---------------------------------------------------------------------------
__device__ __forceinline__ void load_row100(unsigned long long* wp,
                                            const float* row) {
    const float4* r4 = (const float4*)row;
#pragma unroll
    for (int q = 0; q < 25; q++) {
        const float4 v = __ldg(r4 + q);
        asm("mov.b64 %0, {%1, %2};" : "=l"(wp[2 * q])     : "f"(v.x), "f"(v.y));
        asm("mov.b64 %0, {%1, %2};" : "=l"(wp[2 * q + 1]) : "f"(v.z), "f"(v.w));
    }
}

__device__ __forceinline__ float dot100(const unsigned long long* wp,
                                        const float* vec) {
    const ulonglong2* hp = (const ulonglong2*)vec;
    unsigned long long a0 = 0ull, a1 = 0ull, a2 = 0ull, a3 = 0ull;
#pragma unroll
    for (int q = 0; q < 25; q++) {
        const ulonglong2 hv = hp[q];
        if (q & 1) { FMA2(a1, wp[2 * q], hv.x); FMA2(a3, wp[2 * q + 1], hv.y); }
        else       { FMA2(a0, wp[2 * q], hv.x); FMA2(a2, wp[2 * q + 1], hv.y); }
    }
    unsigned long long s01, s23, ssum;
    asm("add.rn.f32x2 %0, %1, %2;" : "=l"(s01)  : "l"(a0),  "l"(a1));
    asm("add.rn.f32x2 %0, %1, %2;" : "=l"(s23)  : "l"(a2),  "l"(a3));
    asm("add.rn.f32x2 %0, %1, %2;" : "=l"(ssum) : "l"(s01), "l"(s23));
    float lo, hi;
    asm("mov.b64 {%0, %1}, %2;" : "=f"(lo), "=f"(hi) : "l"(ssum));
    return lo + hi;
}

__device__ __forceinline__ void load_row208(unsigned long long* wp,
                                            const float* row) {
    const float4* r4 = (const float4*)row;
#pragma unroll
    for (int q = 0; q < 52; q++) {
        const float4 v = __ldg(r4 + q);
        asm("mov.b64 %0, {%1, %2};" : "=l"(wp[2 * q])     : "f"(v.x), "f"(v.y));
        asm("mov.b64 %0, {%1, %2};" : "=l"(wp[2 * q + 1]) : "f"(v.z), "f"(v.w));
    }
}

__device__ __forceinline__ float dot208(const unsigned long long* wp,
                                        const float* vec) {
    const ulonglong2* hp = (const ulonglong2*)vec;
    unsigned long long a0 = 0ull, a1 = 0ull, a2 = 0ull, a3 = 0ull;
#pragma unroll
    for (int q = 0; q < 52; q++) {
        const ulonglong2 hv = hp[q];
        if (q & 1) { FMA2(a1, wp[2 * q], hv.x); FMA2(a3, wp[2 * q + 1], hv.y); }
        else       { FMA2(a0, wp[2 * q], hv.x); FMA2(a2, wp[2 * q + 1], hv.y); }
    }
    unsigned long long s01, s23, ssum;
    asm("add.rn.f32x2 %0, %1, %2;" : "=l"(s01)  : "l"(a0),  "l"(a1));
    asm("add.rn.f32x2 %0, %1, %2;" : "=l"(s23)  : "l"(a2),  "l"(a3));
    asm("add.rn.f32x2 %0, %1, %2;" : "=l"(ssum) : "l"(s01), "l"(s23));
    float lo, hi;
    asm("mov.b64 {%0, %1}, %2;" : "=f"(lo), "=f"(hi) : "l"(ssum));
    return lo + hi;
}

// ---------------------------------------------------------------------------
// G1: xg0[b,t,:] = seq[b,t,:] @ w_ih_l0^T + b_ih_l0, FMA2 dot kernel.
// Grid 2048 = (b, sub); 160 threads; each thread holds one full 208-wide
// weight row in 104 packed regs (reg budget 65536/160=409 -> no spills);
// seq sub-block staged in SMEM; two 150-row passes cover 300 rows.
// Also resets all pipeline flags (runs before the pipeline, same stream).
// ---------------------------------------------------------------------------
__global__ __launch_bounds__(160, 1) void g1_kernel(
    const float* __restrict__ seq,
    const float* __restrict__ w_ih, const float* __restrict__ b_ih)
{
    extern __shared__ __align__(16) float st[];   // [SUB][208]
    const int tid = threadIdx.x;
    const int j   = blockIdx.x;
    const int b   = j & (Bq - 1);
    const int sub = j >> 6;
    const int t0  = sub * SUB;

    if (tid == 0) { g_claim[j] = 0; g_fl2[j] = 0; }
    if (j == 0) {
        if (tid < Bq) { g_fl0[tid] = 0; g_fl1[tid] = 0; }
        if (tid == 64) { g_jobctr = 0; g_g2ctr = 0; }
    }

    const uint32_t st_sa = (uint32_t)__cvta_generic_to_shared(st);
    const float4* src = (const float4*)(seq + ((size_t)b * Sq + t0) * INq);
    for (int i = tid; i < SUB * INq / 4; i += 160)
        cp_async16(st_sa + i * 16, src + i);
    CP_COMMIT(); CP_WAIT(0);
    __syncthreads();

    unsigned long long wp[104];
#pragma unroll
    for (int pass = 0; pass < 2; pass++) {
        const int r = pass * 150 + min(tid, 149);
        load_row208(wp, w_ih + r * INq);
        const float bias = b_ih[r];
        float* dst = g_xg0 + ((size_t)b * Sq + t0) * Gq + r;
#pragma unroll 2
        for (int tt = 0; tt < SUB; tt++) {
            const float v = dot208(wp, st + tt * INq) + bias;
            if (tid < 150) dst[(size_t)tt * Gq] = v;
        }
    }
}

// ---------------------------------------------------------------------------
// Scan SMEM (all arrays indexable by all 384 threads -> guard-free matvec)
// ---------------------------------------------------------------------------
struct GruSmem {
    float h[2][128];        // units 0..99 real
    float hg[384];          // rows 0..299 real
    float ring[4][384];     // L0 xg staging ring
};

// One GRU timestep. RING_XG: xg via gmem cp.async ring (L0); else from the
// SMEM xg_sub block (L1), rows padded to XGP.
template<bool RING_XG>
__device__ __forceinline__ void gru_step(
    int t, int cur, int tid, int jc,
    GruSmem* s, uint32_t ring_sa,
    const unsigned long long* wp, float bhh,
    const float* __restrict__ xg_src,
    float* __restrict__ y_b)
{
    if (RING_XG) {
        int r = t + 3; r = (r < Sq) ? r : (Sq - 1);
        cp_async4(ring_sa + (((t + 3) & 3) * 384 + tid) * 4,
                  xg_src + (size_t)r * Gq + min(tid, Gq - 1));
        CP_COMMIT();
    }

    s->hg[tid] = dot100(wp, s->h[cur]) + bhh;    // uniform, all 384 threads
    __syncthreads();                             // A: hg complete

    if (tid < 128) {
        const float* xgp = RING_XG ? &s->ring[t & 3][0]
                                   : (xg_src + (t & (SUB - 1)) * XGP);
        const float xr = xgp[jc], xz = xgp[Hq + jc], xn = xgp[2 * Hq + jc];
        const float hr = s->hg[jc];
        const float hz = s->hg[Hq + jc];
        const float hn = s->hg[2 * Hq + jc];
        const float hprev = s->h[cur][jc];
        const float r  = __fdividef(1.f, 1.f + __expf(-(xr + hr)));
        const float z  = __fdividef(1.f, 1.f + __expf(-(xz + hz)));
        const float na = xn + r * hn;
        const float e  = __expf(-2.f * fabsf(na));
        const float nt = copysignf(__fdividef(1.f - e, 1.f + e), na);
        const float hnew = (1.f - z) * nt + z * hprev;
        s->h[cur ^ 1][tid] = hnew;
        if (tid < Hq) y_b[(size_t)t * Hq + tid] = hnew;
    }
    if (RING_XG) CP_WAIT(2);
    __syncthreads();                             // B: publish
}

__device__ __forceinline__ void wait_flag(volatile int* f, int target, int tid) {
    if (tid == 0) {
        while (*f < target) __nanosleep(128);
    }
    __syncthreads();
    __threadfence();                             // acquire
}

// ---------------------------------------------------------------------------
// Persistent pipeline: 148 CTAs x 384 threads (== SM count, all co-resident).
//   CTA 0..63    : L0 scan (flags fl0 per 64 steps)
//   CTA 64..127  : L1: per sub, claim-or-consume G2 (inline vs worker-made
//                  xg1p copy), then scan; flags fl1
//   CTA 128..147 : G2 workers off a job queue (claim via CAS) -> G3 pool
// Both G2 paths compute bit-identical values -> output deterministic.
// Dyn SMEM (103424B): ystage[64*100] | xg_sub[64][304]; G3/worker reuse.
// ---------------------------------------------------------------------------
__global__ __launch_bounds__(384, 1) void pipeline_kernel(
    const float* __restrict__ w_hh_l0, const float* __restrict__ b_hh_l0,
    const float* __restrict__ w_ih_l1, const float* __restrict__ b_ih_l1,
    const float* __restrict__ w_hh_l1, const float* __restrict__ b_hh_l1,
    const float* __restrict__ w_out,   const float* __restrict__ b_out,
    const float* __restrict__ h0,      float* __restrict__ out)
{
    extern __shared__ __align__(16) float dyn[];
    __shared__ __align__(16) GruSmem s;
    __shared__ int js, cls;

    const int tid  = threadIdx.x;
    const int role = blockIdx.x;
    const int wr   = min(tid, Gq - 1);
    const int jc   = min(tid, Hq - 1);
    const uint32_t ring_sa  = (uint32_t)__cvta_generic_to_shared(&s.ring[0][0]);
    const uint32_t dyn_sa   = (uint32_t)__cvta_generic_to_shared(dyn);
    const uint32_t xgsub_sa = dyn_sa + SUB * Hq * 4;

    unsigned long long wp[50];

    if (role < Bq) {
        // ---------------- L0 scan ----------------
        const int b = role;
        load_row100(wp, w_hh_l0 + wr * Hq);
        const float bhh = b_hh_l0[wr];
        if (tid < Hq) s.h[0][tid] = h0[b * Hq + tid];
        const float* xg_b = g_xg0 + (size_t)b * Sq * Gq;
        float*       y_b  = g_y0  + (size_t)b * Sq * Hq;

#pragma unroll
        for (int p = 0; p < 3; p++) {
            cp_async4(ring_sa + (p * 384 + tid) * 4,
                      xg_b + (size_t)p * Gq + wr);
            CP_COMMIT();
        }
        CP_WAIT(2);
        __syncthreads();

        for (int t = 0; t < Sq; t += 2) {
            gru_step<true>(t,     0, tid, jc, &s, ring_sa, wp, bhh, xg_b, y_b);
            gru_step<true>(t + 1, 1, tid, jc, &s, ring_sa, wp, bhh, xg_b, y_b);
            if (((t + 2) & (SUB - 1)) == 0) {
                __threadfence();
                __syncthreads();
                if (tid == 0) atomicExch(g_fl0 + b, (t + 2) / SUB);
            }
        }
    } else if (role < 2 * Bq) {
        // ---------------- L1: claim-or-consume G2, then scan ----------------
        const int b = role - Bq;
        const float* y0_b = g_y0 + (size_t)b * Sq * Hq;
        float*       y1_b = g_y1 + (size_t)b * Sq * Hq;
        float* ystage = dyn;                     // [SUB*Hq]
        float* xg_sub = dyn + SUB * Hq;          // [SUB][XGP]
        const int col = min(tid, XGP - 1);
        if (tid < Hq) s.h[0][tid] = h0[Bq * Hq + b * Hq + tid];
        __syncthreads();

        for (int sub = 0; sub < NSUB; sub++) {
            const int t0 = sub * SUB;
            const int j  = sub * Bq + b;

            if (tid == 0) cls = atomicCAS(&g_claim[j], 0, 2);
            __syncthreads();
            const int owner = cls;
            __syncthreads();

            if (owner == 0) {
                // inline path: stage y0, compute G2 into SMEM
                wait_flag(g_fl0 + b, sub + 1, tid);
                const float4* src = (const float4*)(y0_b + (size_t)t0 * Hq);
                for (int i = tid; i < SUB * Hq / 4; i += 384)
                    cp_async16(dyn_sa + i * 16, src + i);
                CP_COMMIT(); CP_WAIT(0);
                __syncthreads();

                load_row100(wp, w_ih_l1 + wr * Hq);
                const float bih = b_ih_l1[wr];
#pragma unroll 2
                for (int tt = 0; tt < SUB; tt++)
                    xg_sub[tt * XGP + col] = dot100(wp, ystage + tt * Hq) + bih;
                __syncthreads();
            } else {
                // consume path: a worker produced xg1p[b,sub] — block copy
                wait_flag(g_fl2 + j, 1, tid);
                const float4* src = (const float4*)(g_xg1p +
                                    ((size_t)b * Sq + t0) * XGP);
                for (int i = tid; i < SUB * XGP / 4; i += 384)
                    cp_async16(xgsub_sa + i * 16, src + i);
                CP_COMMIT(); CP_WAIT(0);
                __syncthreads();
            }

            // scan the sub-block
            load_row100(wp, w_hh_l1 + wr * Hq);
            const float bhh = b_hh_l1[wr];
            for (int t = t0; t < t0 + SUB; t += 2) {
                gru_step<false>(t,     0, tid, jc, &s, ring_sa, wp, bhh,
                                xg_sub, y1_b);
                gru_step<false>(t + 1, 1, tid, jc, &s, ring_sa, wp, bhh,
                                xg_sub, y1_b);
            }
            __threadfence();
            __syncthreads();
            if (tid == 0) atomicExch(g_fl1 + b, sub + 1);
        }
    } else {
        // ---------------- G2 workers ----------------
        load_row100(wp, w_ih_l1 + wr * Hq);
        const float bih = b_ih_l1[wr];

        for (;;) {
            if (tid == 0) js = atomicAdd(&g_g2ctr, 1);
            __syncthreads();
            const int j = js;
            __syncthreads();
            if (j >= NJOB2) break;

            if (tid == 0) cls = atomicCAS(&g_claim[j], 0, 1);
            __syncthreads();
            const int got = cls;
            __syncthreads();
            if (got != 0) continue;              // L1 already inlined it

            const int b = j & (Bq - 1), sub = j >> 6, t0 = sub * SUB;
            wait_flag(g_fl0 + b, sub + 1, tid);

            const float4* src = (const float4*)(g_y0 +
                                ((size_t)b * Sq + t0) * Hq);
            for (int i = tid; i < SUB * Hq / 4; i += 384)
                cp_async16(dyn_sa + i * 16, src + i);
            CP_COMMIT(); CP_WAIT(0);
            __syncthreads();

            float* dst = g_xg1p + ((size_t)b * Sq + t0) * XGP + wr;
#pragma unroll 2
            for (int tt = 0; tt < SUB; tt++) {
                const float v = dot100(wp, dyn + tt * Hq) + bih;
                if (tid < Gq) dst[(size_t)tt * XGP] = v;
            }
            __threadfence();
            __syncthreads();
            if (tid == 0) atomicExch(&g_fl2[j], 1);
            __syncthreads();                     // protect dyn (WAR)
        }
    }

    // ---------------- G3 pool: out = y1 @ w_out^T + b_out ----------------
    {
        const int nidx = tid & 127;
        const int tq   = tid >> 7;               // 0..2
        const int nr   = min(nidx, OUTq - 1);
        load_row100(wp, w_out + nr * Hq);
        const float bo = b_out[nr];

        for (;;) {
            if (tid == 0) js = atomicAdd(&g_jobctr, 1);
            __syncthreads();
            const int j = js;
            __syncthreads();
            if (j >= Bq * 16) break;             // 1024 jobs of 128 steps
            const int b   = j & (Bq - 1);
            const int blk = j >> 6;              // 0..15

            wait_flag(g_fl1 + b, 2 * blk + 2, tid);

            const float4* src = (const float4*)(g_y1 +
                                ((size_t)b * Sq + blk * 128) * Hq);
            for (int i = tid; i < 128 * Hq / 4; i += 384)
                cp_async16(dyn_sa + i * 16, src + i);
            CP_COMMIT(); CP_WAIT(0);
            __syncthreads();

            if (nidx < OUTq) {
                float* ob = out + ((size_t)b * Sq + blk * 128) * OUTq;
                for (int tt = tq; tt < 128; tt += 3)
                    ob[(size_t)tt * OUTq + nidx] = dot100(wp, dyn + tt * Hq) + bo;
            }
            __syncthreads();                     // protect stage (WAR)
        }
    }
}

// ---------------------------------------------------------------------------
// Launch: g1 (FMA2 dot kernel, also resets flags) -> persistent pipeline.
// One stream, graph-capturable, no allocations.
// ---------------------------------------------------------------------------
extern "C" void kernel_launch(void* const* d_in, const int* in_sizes, int n_in,
                              void* d_out, int out_size)
{
    (void)in_sizes; (void)n_in; (void)out_size;
    const float* seq     = (const float*)d_in[0];
    const float* h0      = (const float*)d_in[1];   // [2][B][H]
    const float* w_ih_l0 = (const float*)d_in[2];
    const float* w_hh_l0 = (const float*)d_in[3];
    const float* b_ih_l0 = (const float*)d_in[4];
    const float* b_hh_l0 = (const float*)d_in[5];
    const float* w_ih_l1 = (const float*)d_in[6];
    const float* w_hh_l1 = (const float*)d_in[7];
    const float* b_ih_l1 = (const float*)d_in[8];
    const float* b_hh_l1 = (const float*)d_in[9];
    const float* w_out   = (const float*)d_in[10];
    const float* b_out   = (const float*)d_in[11];
    float* out = (float*)d_out;

    const int G1_BYTES  = SUB * INq * 4;                 // 53248
    const int DYN_BYTES = (SUB * Hq + SUB * XGP) * 4;    // 103424
    cudaFuncSetAttribute(g1_kernel,
                         cudaFuncAttributeMaxDynamicSharedMemorySize, G1_BYTES);
    cudaFuncSetAttribute(pipeline_kernel,
                         cudaFuncAttributeMaxDynamicSharedMemorySize, DYN_BYTES);

    g1_kernel<<<NJOB2, 160, G1_BYTES>>>(seq, w_ih_l0, b_ih_l0);

    pipeline_kernel<<<148, 384, DYN_BYTES>>>(
        w_hh_l0, b_hh_l0,
        w_ih_l1, b_ih_l1, w_hh_l1, b_hh_l1,
        w_out, b_out, h0, out);
}

// round 12
// speedup vs baseline: 1.9811x; 1.0992x over previous
#include <cuda_runtime.h>
#include <cstdint>

// Problem constants
#define Bq   64
#define Sq   2048
#define INq  208
#define Hq   100
#define Gq   300      // 3*H gate rows
#define OUTq 98
#define Mq   (Bq * Sq)   // 131072 rows

#define SUB   64          // handoff granularity (steps)
#define NSUB  (Sq / SUB)  // 32
#define NJOB2 (Bq * NSUB) // 2048 G2 jobs
#define XGP   304         // padded xg1 row stride (floats, 16B-aligned)
#define PT    320         // pipeline threads (300 real + 20 pad)

// ---------------------------------------------------------------------------
// Scratch (static __device__ arrays — allocation is forbidden)
// ---------------------------------------------------------------------------
__device__ float g_xg0 [(size_t)Mq * Gq];   // layer-0 input gates (G1 out)
__device__ float g_xg1p[(size_t)Mq * XGP];  // layer-1 input gates, padded rows
__device__ float g_y0  [(size_t)Mq * Hq];   // layer-0 hidden sequence
__device__ float g_y1  [(size_t)Mq * Hq];   // layer-1 hidden sequence
__device__ int   g_fl0[Bq];                 // L0 sub-blocks done per batch
__device__ int   g_fl1[Bq];                 // L1 sub-blocks done per batch
__device__ int   g_fl2[NJOB2];              // per-job xg1 ready
__device__ int   g_claim[NJOB2];            // 0=free 1=worker 2=L1-inline
__device__ int   g_jobctr;                  // G3 job counter
__device__ int   g_g2ctr;                   // G2 worker job counter

#define FMA2(c, a, b) \
    asm("fma.rn.f32x2 %0, %1, %2, %0;" : "+l"(c) : "l"(a), "l"(b))

__device__ __forceinline__ void cp_async4(uint32_t saddr, const float* gptr) {
    asm volatile("cp.async.ca.shared.global [%0], [%1], 4;"
                 :: "r"(saddr), "l"(gptr));
}
__device__ __forceinline__ void cp_async16(uint32_t saddr, const void* gptr) {
    asm volatile("cp.async.cg.shared.global [%0], [%1], 16;"
                 :: "r"(saddr), "l"(gptr));
}
#define CP_COMMIT()  asm volatile("cp.async.commit_group;" ::: "memory")
#define CP_WAIT(n)   asm volatile("cp.async.wait_group %0;" :: "n"(n) : "memory")

// ---------------------------------------------------------------------------
// Packed-dot helpers
// ---------------------------------------------------------------------------
__device__ __forceinline__ void load_row100(unsigned long long* wp,
                                            const float* row) {
    const float4* r4 = (const float4*)row;
#pragma unroll
    for (int q = 0; q < 25; q++) {
        const float4 v = __ldg(r4 + q);
        asm("mov.b64 %0, {%1, %2};" : "=l"(wp[2 * q])     : "f"(v.x), "f"(v.y));
        asm("mov.b64 %0, {%1, %2};" : "=l"(wp[2 * q + 1]) : "f"(v.z), "f"(v.w));
    }
}

__device__ __forceinline__ float dot100(const unsigned long long* wp,
                                        const float* vec) {
    const ulonglong2* hp = (const ulonglong2*)vec;
    unsigned long long a0 = 0ull, a1 = 0ull, a2 = 0ull, a3 = 0ull;
#pragma unroll
    for (int q = 0; q < 25; q++) {
        const ulonglong2 hv = hp[q];
        if (q & 1) { FMA2(a1, wp[2 * q], hv.x); FMA2(a3, wp[2 * q + 1], hv.y); }
        else       { FMA2(a0, wp[2 * q], hv.x); FMA2(a2, wp[2 * q + 1], hv.y); }
    }
    unsigned long long s01, s23, ssum;
    asm("add.rn.f32x2 %0, %1, %2;" : "=l"(s01)  : "l"(a0),  "l"(a1));
    asm("add.rn.f32x2 %0, %1, %2;" : "=l"(s23)  : "l"(a2),  "l"(a3));
    asm("add.rn.f32x2 %0, %1, %2;" : "=l"(ssum) : "l"(s01), "l"(s23));
    float lo, hi;
    asm("mov.b64 {%0, %1}, %2;" : "=f"(lo), "=f"(hi) : "l"(ssum));
    return lo + hi;
}

__device__ __forceinline__ void load_row208(unsigned long long* wp,
                                            const float* row) {
    const float4* r4 = (const float4*)row;
#pragma unroll
    for (int q = 0; q < 52; q++) {
        const float4 v = __ldg(r4 + q);
        asm("mov.b64 %0, {%1, %2};" : "=l"(wp[2 * q])     : "f"(v.x), "f"(v.y));
        asm("mov.b64 %0, {%1, %2};" : "=l"(wp[2 * q + 1]) : "f"(v.z), "f"(v.w));
    }
}

__device__ __forceinline__ float dot208(const unsigned long long* wp,
                                        const float* vec) {
    const ulonglong2* hp = (const ulonglong2*)vec;
    unsigned long long a0 = 0ull, a1 = 0ull, a2 = 0ull, a3 = 0ull;
#pragma unroll
    for (int q = 0; q < 52; q++) {
        const ulonglong2 hv = hp[q];
        if (q & 1) { FMA2(a1, wp[2 * q], hv.x); FMA2(a3, wp[2 * q + 1], hv.y); }
        else       { FMA2(a0, wp[2 * q], hv.x); FMA2(a2, wp[2 * q + 1], hv.y); }
    }
    unsigned long long s01, s23, ssum;
    asm("add.rn.f32x2 %0, %1, %2;" : "=l"(s01)  : "l"(a0),  "l"(a1));
    asm("add.rn.f32x2 %0, %1, %2;" : "=l"(s23)  : "l"(a2),  "l"(a3));
    asm("add.rn.f32x2 %0, %1, %2;" : "=l"(ssum) : "l"(s01), "l"(s23));
    float lo, hi;
    asm("mov.b64 {%0, %1}, %2;" : "=f"(lo), "=f"(hi) : "l"(ssum));
    return lo + hi;
}

// ---------------------------------------------------------------------------
// G1: xg0 = seq @ w_ih_l0^T + b_ih_l0 (at its FMA2-rt3 issue floor; keep).
// Grid 2048 (sub-major), 160 threads, reg-resident 208-wide rows.
// Also resets all pipeline flags.
// ---------------------------------------------------------------------------
__global__ __launch_bounds__(160, 1) void g1_kernel(
    const float* __restrict__ seq,
    const float* __restrict__ w_ih, const float* __restrict__ b_ih)
{
    extern __shared__ __align__(16) float st[];   // [SUB][208]
    const int tid = threadIdx.x;
    const int j   = blockIdx.x;
    const int b   = j & (Bq - 1);
    const int sub = j >> 6;
    const int t0  = sub * SUB;

    if (tid == 0) { g_claim[j] = 0; g_fl2[j] = 0; }
    if (j == 0) {
        if (tid < Bq) { g_fl0[tid] = 0; g_fl1[tid] = 0; }
        if (tid == 64) { g_jobctr = 0; g_g2ctr = 0; }
    }

    const uint32_t st_sa = (uint32_t)__cvta_generic_to_shared(st);
    const float4* src = (const float4*)(seq + ((size_t)b * Sq + t0) * INq);
    for (int i = tid; i < SUB * INq / 4; i += 160)
        cp_async16(st_sa + i * 16, src + i);
    CP_COMMIT(); CP_WAIT(0);
    __syncthreads();

    unsigned long long wp[104];
#pragma unroll
    for (int pass = 0; pass < 2; pass++) {
        const int r = pass * 150 + min(tid, 149);
        load_row208(wp, w_ih + r * INq);
        const float bias = b_ih[r];
        float* dst = g_xg0 + ((size_t)b * Sq + t0) * Gq + r;
#pragma unroll 2
        for (int tt = 0; tt < SUB; tt++) {
            const float v = dot208(wp, st + tt * INq) + bias;
            if (tid < 150) dst[(size_t)tt * Gq] = v;
        }
    }
}

// ---------------------------------------------------------------------------
// Scan SMEM (all arrays indexable by all PT threads -> guard-free matvec)
// ---------------------------------------------------------------------------
struct GruSmem {
    float h[2][128];        // units 0..99 real
    float hg[PT];           // rows 0..299 real
    float ring[4][PT];      // xg staging ring
};

// Ring-streaming GRU step: xg prefetched from gmem (stride/clamp params let
// L0 stream xg0 rows and L1 stream padded xg1p rows within a sub).
__device__ __forceinline__ void gru_step_ring(
    int t, int cur, int tid, int jc, int wr,
    GruSmem* s, uint32_t ring_sa,
    const unsigned long long* wp, float bhh,
    const float* __restrict__ xg_base, int stride, int rmax,
    float* __restrict__ y_b)
{
    const int r = min(t + 3, rmax);
    cp_async4(ring_sa + (((t + 3) & 3) * PT + tid) * 4,
              xg_base + (size_t)r * stride + wr);
    CP_COMMIT();

    s->hg[tid] = dot100(wp, s->h[cur]) + bhh;    // uniform, all PT threads
    __syncthreads();                             // A: hg complete

    if (tid < 128) {
        const float* xgp = &s->ring[t & 3][0];
        const float xr = xgp[jc], xz = xgp[Hq + jc], xn = xgp[2 * Hq + jc];
        const float hr = s->hg[jc];
        const float hz = s->hg[Hq + jc];
        const float hn = s->hg[2 * Hq + jc];
        const float hprev = s->h[cur][jc];
        const float r_  = __fdividef(1.f, 1.f + __expf(-(xr + hr)));
        const float z   = __fdividef(1.f, 1.f + __expf(-(xz + hz)));
        const float na  = xn + r_ * hn;
        const float e   = __expf(-2.f * fabsf(na));
        const float nt  = copysignf(__fdividef(1.f - e, 1.f + e), na);
        const float hnew = (1.f - z) * nt + z * hprev;
        s->h[cur ^ 1][tid] = hnew;
        if (tid < Hq) y_b[(size_t)t * Hq + tid] = hnew;
    }
    CP_WAIT(2);                                  // ring slot t+1 landed
    __syncthreads();                             // B: publish
}

// SMEM-xg GRU step (L1 inline path; xg_sub rows padded to XGP)
__device__ __forceinline__ void gru_step_smem(
    int t, int cur, int tid, int jc,
    GruSmem* s,
    const unsigned long long* wp, float bhh,
    const float* __restrict__ xg_sub,
    float* __restrict__ y_b)
{
    s->hg[tid] = dot100(wp, s->h[cur]) + bhh;
    __syncthreads();                             // A

    if (tid < 128) {
        const float* xgp = xg_sub + (t & (SUB - 1)) * XGP;
        const float xr = xgp[jc], xz = xgp[Hq + jc], xn = xgp[2 * Hq + jc];
        const float hr = s->hg[jc];
        const float hz = s->hg[Hq + jc];
        const float hn = s->hg[2 * Hq + jc];
        const float hprev = s->h[cur][jc];
        const float r_  = __fdividef(1.f, 1.f + __expf(-(xr + hr)));
        const float z   = __fdividef(1.f, 1.f + __expf(-(xz + hz)));
        const float na  = xn + r_ * hn;
        const float e   = __expf(-2.f * fabsf(na));
        const float nt  = copysignf(__fdividef(1.f - e, 1.f + e), na);
        const float hnew = (1.f - z) * nt + z * hprev;
        s->h[cur ^ 1][tid] = hnew;
        if (tid < Hq) y_b[(size_t)t * Hq + tid] = hnew;
    }
    __syncthreads();                             // B
}

// stage 3 ring rows t0..t0+2 (clamped); leaves <=2 groups pending
__device__ __forceinline__ void ring_prologue(
    uint32_t ring_sa, const float* xg_base, int stride, int t0, int rmax,
    int tid, int wr)
{
#pragma unroll
    for (int p = 0; p < 3; p++) {
        cp_async4(ring_sa + (((t0 + p) & 3) * PT + tid) * 4,
                  xg_base + (size_t)min(t0 + p, rmax) * stride + wr);
        CP_COMMIT();
    }
    CP_WAIT(2);
    __syncthreads();
}

__device__ __forceinline__ void wait_flag(volatile int* f, int target, int tid) {
    if (tid == 0) {
        while (*f < target) __nanosleep(128);
    }
    __syncthreads();
    __threadfence();                             // acquire
}

// ---------------------------------------------------------------------------
// Persistent pipeline: 148 CTAs x PT threads (all co-resident).
//   CTA 0..63    : L0 scan (ring from g_xg0), flags fl0 per 64 steps,
//                  then G2 queue, then G3 pool
//   CTA 64..127  : L1: per sub claim-or-consume (inline G2 in SMEM, or
//                  ring-stream worker-made xg1p), then G3 pool
//   CTA 128..147 : G2 workers -> G3 pool
// ---------------------------------------------------------------------------
__global__ __launch_bounds__(PT, 1) void pipeline_kernel(
    const float* __restrict__ w_hh_l0, const float* __restrict__ b_hh_l0,
    const float* __restrict__ w_ih_l1, const float* __restrict__ b_ih_l1,
    const float* __restrict__ w_hh_l1, const float* __restrict__ b_hh_l1,
    const float* __restrict__ w_out,   const float* __restrict__ b_out,
    const float* __restrict__ h0,      float* __restrict__ out)
{
    extern __shared__ __align__(16) float dyn[];
    __shared__ __align__(16) GruSmem s;
    __shared__ int js, cls;

    const int tid  = threadIdx.x;
    const int role = blockIdx.x;
    const int wr   = min(tid, Gq - 1);
    const int jc   = min(tid, Hq - 1);
    const uint32_t ring_sa = (uint32_t)__cvta_generic_to_shared(&s.ring[0][0]);
    const uint32_t dyn_sa  = (uint32_t)__cvta_generic_to_shared(dyn);

    unsigned long long wp[50];
    bool do_g2_queue = (role >= 2 * Bq);   // workers start on G2 immediately

    if (role < Bq) {
        // ---------------- L0 scan ----------------
        const int b = role;
        load_row100(wp, w_hh_l0 + wr * Hq);
        const float bhh = b_hh_l0[wr];
        if (tid < Hq) s.h[0][tid] = h0[b * Hq + tid];
        const float* xg_b = g_xg0 + (size_t)b * Sq * Gq;
        float*       y_b  = g_y0  + (size_t)b * Sq * Hq;

        ring_prologue(ring_sa, xg_b, Gq, 0, Sq - 1, tid, wr);

        for (int t = 0; t < Sq; t += 2) {
            gru_step_ring(t,     0, tid, jc, wr, &s, ring_sa, wp, bhh,
                          xg_b, Gq, Sq - 1, y_b);
            gru_step_ring(t + 1, 1, tid, jc, wr, &s, ring_sa, wp, bhh,
                          xg_b, Gq, Sq - 1, y_b);
            if (((t + 2) & (SUB - 1)) == 0) {
                __threadfence();
                __syncthreads();
                if (tid == 0) atomicExch(g_fl0 + b, (t + 2) / SUB);
            }
        }
        do_g2_queue = true;                      // help finish G2, then G3
    } else if (role < 2 * Bq) {
        // ---------------- L1 ----------------
        const int b = role - Bq;
        const float* y0_b  = g_y0 + (size_t)b * Sq * Hq;
        float*       y1_b  = g_y1 + (size_t)b * Sq * Hq;
        const float* xgp_b = g_xg1p + (size_t)b * Sq * XGP;
        float* ystage = dyn;                     // [SUB*Hq]
        float* xg_sub = dyn + SUB * Hq;          // [SUB][XGP]
        const int col = min(tid, XGP - 1);
        if (tid < Hq) s.h[0][tid] = h0[Bq * Hq + b * Hq + tid];
        __syncthreads();

        // preload recurrent weights once; inline path reloads around G2
        load_row100(wp, w_hh_l1 + wr * Hq);
        float bhh = b_hh_l1[wr];

        for (int sub = 0; sub < NSUB; sub++) {
            const int t0 = sub * SUB;
            const int j  = sub * Bq + b;

            if (tid == 0) cls = atomicCAS(&g_claim[j], 0, 2);
            __syncthreads();
            const int owner = cls;
            __syncthreads();

            if (owner == 0) {
                // inline: stage y0 -> compute G2 into SMEM -> scan from SMEM
                wait_flag(g_fl0 + b, sub + 1, tid);
                const float4* src = (const float4*)(y0_b + (size_t)t0 * Hq);
                for (int i = tid; i < SUB * Hq / 4; i += PT)
                    cp_async16(dyn_sa + i * 16, src + i);
                CP_COMMIT(); CP_WAIT(0);
                __syncthreads();

                load_row100(wp, w_ih_l1 + wr * Hq);
                const float bih = b_ih_l1[wr];
#pragma unroll 2
                for (int tt = 0; tt < SUB; tt++)
                    xg_sub[tt * XGP + col] = dot100(wp, ystage + tt * Hq) + bih;
                __syncthreads();

                load_row100(wp, w_hh_l1 + wr * Hq);
                for (int t = t0; t < t0 + SUB; t += 2) {
                    gru_step_smem(t,     0, tid, jc, &s, wp, bhh, xg_sub, y1_b);
                    gru_step_smem(t + 1, 1, tid, jc, &s, wp, bhh, xg_sub, y1_b);
                }
            } else {
                // consume: ring-stream worker-made xg1p (no block copy)
                wait_flag(g_fl2 + j, 1, tid);
                ring_prologue(ring_sa, xgp_b, XGP, t0, t0 + SUB - 1, tid, wr);
                for (int t = t0; t < t0 + SUB; t += 2) {
                    gru_step_ring(t,     0, tid, jc, wr, &s, ring_sa, wp, bhh,
                                  xgp_b, XGP, t0 + SUB - 1, y1_b);
                    gru_step_ring(t + 1, 1, tid, jc, wr, &s, ring_sa, wp, bhh,
                                  xgp_b, XGP, t0 + SUB - 1, y1_b);
                }
            }
            __threadfence();
            __syncthreads();
            if (tid == 0) atomicExch(g_fl1 + b, sub + 1);
        }
    }

    // ---------------- G2 queue (workers from start; L0 CTAs after scan) ----
    if (do_g2_queue) {
        load_row100(wp, w_ih_l1 + wr * Hq);
        const float bih = b_ih_l1[wr];

        for (;;) {
            if (tid == 0) js = atomicAdd(&g_g2ctr, 1);
            __syncthreads();
            const int j = js;
            __syncthreads();
            if (j >= NJOB2) break;

            if (tid == 0) cls = atomicCAS(&g_claim[j], 0, 1);
            __syncthreads();
            const int got = cls;
            __syncthreads();
            if (got != 0) continue;              // L1 already inlined it

            const int b = j & (Bq - 1), sub = j >> 6, t0 = sub * SUB;
            wait_flag(g_fl0 + b, sub + 1, tid);

            const float4* src = (const float4*)(g_y0 +
                                ((size_t)b * Sq + t0) * Hq);
            for (int i = tid; i < SUB * Hq / 4; i += PT)
                cp_async16(dyn_sa + i * 16, src + i);
            CP_COMMIT(); CP_WAIT(0);
            __syncthreads();

            float* dst = g_xg1p + ((size_t)b * Sq + t0) * XGP + wr;
#pragma unroll 2
            for (int tt = 0; tt < SUB; tt++) {
                const float v = dot100(wp, dyn + tt * Hq) + bih;
                if (tid < Gq) dst[(size_t)tt * XGP] = v;
            }
            __threadfence();
            __syncthreads();
            if (tid == 0) atomicExch(&g_fl2[j], 1);
            __syncthreads();                     // protect dyn (WAR)
        }
    }

    // ---------------- G3 pool: out = y1 @ w_out^T + b_out ----------------
    {
        const int nidx = tid % 160;              // 2 groups of 160
        const int tq   = tid / 160;              // 0..1
        const int nr   = min(nidx, OUTq - 1);
        load_row100(wp, w_out + nr * Hq);
        const float bo = b_out[nr];

        for (;;) {
            if (tid == 0) js = atomicAdd(&g_jobctr, 1);
            __syncthreads();
            const int j = js;
            __syncthreads();
            if (j >= Bq * 16) break;             // 1024 jobs of 128 steps
            const int b   = j & (Bq - 1);
            const int blk = j >> 6;              // 0..15

            wait_flag(g_fl1 + b, 2 * blk + 2, tid);

            const float4* src = (const float4*)(g_y1 +
                                ((size_t)b * Sq + blk * 128) * Hq);
            for (int i = tid; i < 128 * Hq / 4; i += PT)
                cp_async16(dyn_sa + i * 16, src + i);
            CP_COMMIT(); CP_WAIT(0);
            __syncthreads();

            if (nidx < OUTq) {
                float* ob = out + ((size_t)b * Sq + blk * 128) * OUTq;
                for (int tt = tq; tt < 128; tt += 2)
                    ob[(size_t)tt * OUTq + nidx] = dot100(wp, dyn + tt * Hq) + bo;
            }
            __syncthreads();                     // protect stage (WAR)
        }
    }
}

// ---------------------------------------------------------------------------
// Launch: g1 (also resets flags) -> persistent pipeline.
// One stream, graph-capturable, no allocations.
// ---------------------------------------------------------------------------
extern "C" void kernel_launch(void* const* d_in, const int* in_sizes, int n_in,
                              void* d_out, int out_size)
{
    (void)in_sizes; (void)n_in; (void)out_size;
    const float* seq     = (const float*)d_in[0];
    const float* h0      = (const float*)d_in[1];   // [2][B][H]
    const float* w_ih_l0 = (const float*)d_in[2];
    const float* w_hh_l0 = (const float*)d_in[3];
    const float* b_ih_l0 = (const float*)d_in[4];
    const float* b_hh_l0 = (const float*)d_in[5];
    const float* w_ih_l1 = (const float*)d_in[6];
    const float* w_hh_l1 = (const float*)d_in[7];
    const float* b_ih_l1 = (const float*)d_in[8];
    const float* b_hh_l1 = (const float*)d_in[9];
    const float* w_out   = (const float*)d_in[10];
    const float* b_out   = (const float*)d_in[11];
    float* out = (float*)d_out;

    const int G1_BYTES  = SUB * INq * 4;                 // 53248
    const int DYN_BYTES = (SUB * Hq + SUB * XGP) * 4;    // 103424
    cudaFuncSetAttribute(g1_kernel,
                         cudaFuncAttributeMaxDynamicSharedMemorySize, G1_BYTES);
    cudaFuncSetAttribute(pipeline_kernel,
                         cudaFuncAttributeMaxDynamicSharedMemorySize, DYN_BYTES);

    g1_kernel<<<NJOB2, 160, G1_BYTES>>>(seq, w_ih_l0, b_ih_l0);

    pipeline_kernel<<<148, PT, DYN_BYTES>>>(
        w_hh_l0, b_hh_l0,
        w_ih_l1, b_ih_l1, w_hh_l1, b_hh_l1,
        w_out, b_out, h0, out);
}